// round 1
// baseline (speedup 1.0000x reference)
#include <cuda_runtime.h>
#include <math.h>

#define BB 2
#define CIN 64
#define CC 64
#define HIN 96
#define HH 48
#define NN (HH*HH)      /* 2304 */
#define KK 7
#define NROWS (BB*NN)   /* 4608 */

// ---------------- scratch (device globals; no allocation) ----------------
__device__ float g_feat[NROWS*CC];            // [b*N+n][c]
__device__ float g_sq[NROWS];
__device__ float g_dist[(size_t)NROWS*NN];    // clamped d^2, 42.5 MB
__device__ int   g_nbr[NROWS*KK];             // global row indices of 7-NN
__device__ float g_Wh[NROWS*CC];
__device__ float g_s1[NROWS];
__device__ float g_s2[NROWS];
__device__ float g_hcat[(size_t)NROWS*2*CC];
__device__ float g_gT[(size_t)BB*CC*NN];      // [b][c][n] == [b][c][h][w]

// ---------------- stage 1: stride-2 conv, pad 1 ----------------
__global__ void conv_kernel(const float* __restrict__ x, const float* __restrict__ w,
                            const float* __restrict__ bias) {
    int idx = blockIdx.x * blockDim.x + threadIdx.x;
    if (idx >= BB*NN*CC) return;
    int co = idx % CC;
    int n  = (idx / CC) % NN;
    int b  = idx / (CC*NN);
    int oh = n / HH, ow = n % HH;
    int ih0 = oh*2 - 1, iw0 = ow*2 - 1;
    float acc = bias[co];
    for (int ci = 0; ci < CIN; ci++) {
        const float* xp = x + ((size_t)(b*CIN + ci))*HIN*HIN;
        const float* wp = w + ((size_t)(co*CIN + ci))*9;
        #pragma unroll
        for (int kh = 0; kh < 3; kh++) {
            int ih = ih0 + kh; if ((unsigned)ih >= HIN) continue;
            #pragma unroll
            for (int kw = 0; kw < 3; kw++) {
                int iw = iw0 + kw; if ((unsigned)iw >= HIN) continue;
                acc += xp[ih*HIN + iw] * wp[kh*3 + kw];
            }
        }
    }
    g_feat[(size_t)(b*NN + n)*CC + co] = acc;
}

// ---------------- stage 2: squared norms ----------------
__global__ void sq_kernel() {
    int r = blockIdx.x * blockDim.x + threadIdx.x;
    if (r >= NROWS) return;
    float s = 0.f;
    const float* f = &g_feat[(size_t)r*CC];
    #pragma unroll
    for (int c = 0; c < CC; c++) s += f[c]*f[c];
    g_sq[r] = s;
}

// ---------------- stage 3: clamped squared-distance matrix (tiled) ----------------
__global__ void dist_kernel() {
    int b  = blockIdx.z;
    int i0 = blockIdx.y * 32, j0 = blockIdx.x * 32;
    __shared__ float As[32][65];
    __shared__ float Bs[32][65];
    int tx = threadIdx.x, ty = threadIdx.y;
    for (int c = tx; c < CC; c += 32) {
        As[ty][c] = g_feat[(size_t)(b*NN + i0 + ty)*CC + c];
        Bs[ty][c] = g_feat[(size_t)(b*NN + j0 + ty)*CC + c];
    }
    __syncthreads();
    float dot = 0.f;
    #pragma unroll
    for (int c = 0; c < CC; c++) dot += As[ty][c] * Bs[tx][c];
    float d2 = g_sq[b*NN + i0 + ty] + g_sq[b*NN + j0 + tx] - 2.f*dot;
    g_dist[(size_t)(b*NN + i0 + ty)*NN + (j0 + tx)] = fmaxf(d2, 0.f);
}

// ---------------- stage 4: stable 7-NN selection per row ----------------
__global__ void topk_kernel() {
    int row = blockIdx.x;           // b*N + i
    __shared__ float sd[NN];
    __shared__ float rmin[256];
    __shared__ int   rid[256];
    const float* dr = &g_dist[(size_t)row*NN];
    for (int j = threadIdx.x; j < NN; j += 256) sd[j] = dr[j];
    __syncthreads();
    int bbase = (row / NN) * NN;
    for (int k = 0; k < KK; k++) {
        float best = INFINITY; int bj = NN;
        for (int j = threadIdx.x; j < NN; j += 256) {
            float v = sd[j];
            if (v < best) { best = v; bj = j; }   // strict: keeps smallest index on ties
        }
        rmin[threadIdx.x] = best; rid[threadIdx.x] = bj;
        __syncthreads();
        for (int s = 128; s > 0; s >>= 1) {
            if (threadIdx.x < s) {
                float v = rmin[threadIdx.x + s]; int j = rid[threadIdx.x + s];
                if (v < rmin[threadIdx.x] ||
                    (v == rmin[threadIdx.x] && j < rid[threadIdx.x])) {
                    rmin[threadIdx.x] = v; rid[threadIdx.x] = j;
                }
            }
            __syncthreads();
        }
        if (threadIdx.x == 0) {
            g_nbr[row*KK + k] = bbase + rid[0];
            sd[rid[0]] = INFINITY;
        }
        __syncthreads();
    }
}

// ---------------- stage 5: per-row linear + attention scalars ----------------
// Wh = in @ W ; s1 = Wh . a[:64] ; s2 = Wh . a[64:]
__global__ void linear64_kernel(const float* __restrict__ W, const float* __restrict__ a) {
    int row = blockIdx.x;
    int f = threadIdx.x;   // 64
    __shared__ float sin_[64];
    sin_[f] = g_feat[(size_t)row*CC + f];
    __syncthreads();
    float acc = 0.f;
    #pragma unroll
    for (int k = 0; k < 64; k++) acc += sin_[k] * W[k*CC + f];
    g_Wh[(size_t)row*CC + f] = acc;
    __shared__ float r1[CC], r2[CC];
    r1[f] = acc * a[f];
    r2[f] = acc * a[CC + f];
    __syncthreads();
    for (int s = CC/2; s > 0; s >>= 1) {
        if (f < s) { r1[f] += r1[f+s]; r2[f] += r2[f+s]; }
        __syncthreads();
    }
    if (f == 0) { g_s1[row] = r1[0]; g_s2[row] = r2[0]; }
}

__global__ void linear128_kernel(const float* __restrict__ W, const float* __restrict__ a) {
    int row = blockIdx.x;
    int f = threadIdx.x;   // 64
    __shared__ float sin_[128];
    sin_[f]      = g_hcat[(size_t)row*128 + f];
    sin_[f + 64] = g_hcat[(size_t)row*128 + f + 64];
    __syncthreads();
    float acc = 0.f;
    #pragma unroll
    for (int k = 0; k < 128; k++) acc += sin_[k] * W[k*CC + f];
    g_Wh[(size_t)row*CC + f] = acc;
    __shared__ float r1[CC], r2[CC];
    r1[f] = acc * a[f];
    r2[f] = acc * a[CC + f];
    __syncthreads();
    for (int s = CC/2; s > 0; s >>= 1) {
        if (f < s) { r1[f] += r1[f+s]; r2[f] += r2[f+s]; }
        __syncthreads();
    }
    if (f == 0) { g_s1[row] = r1[0]; g_s2[row] = r2[0]; }
}

// ---------------- stage 6: sparse GAT aggregation ----------------
// mode 0: write hcat[:, 0:64]; mode 1: write hcat[:, 64:128]; mode 2: write g_gT [b][c][n]
__global__ void gat_agg_kernel(int mode) {
    int row = blockIdx.x;
    int f = threadIdx.x;   // 64
    __shared__ int   jn[KK];
    __shared__ float se[KK];
    if (f < KK) {
        int j = g_nbr[row*KK + f];
        jn[f] = j;
        float v = g_s1[row] + g_s2[j];
        se[f] = v > 0.f ? v : 0.2f * v;       // leaky relu
    }
    __syncthreads();
    float mx = -INFINITY;
    #pragma unroll
    for (int k = 0; k < KK; k++) mx = fmaxf(mx, se[k]);
    float wk[KK]; float sum = 0.f;
    #pragma unroll
    for (int k = 0; k < KK; k++) { wk[k] = expf(se[k] - mx); sum += wk[k]; }
    float inv = 1.f / sum;
    float acc = 0.f;
    #pragma unroll
    for (int k = 0; k < KK; k++) acc += (wk[k]*inv) * g_Wh[(size_t)jn[k]*CC + f];
    acc = acc > 0.f ? acc : (expf(acc) - 1.f);  // elu
    if (mode == 2) {
        int b = row / NN, n = row % NN;
        g_gT[((size_t)(b*CC + f))*NN + n] = acc;
    } else {
        g_hcat[(size_t)row*128 + mode*64 + f] = acc;
    }
}

// ---------------- stage 7: transpose conv (gather form) ----------------
// out[b,co,oh,ow] = bias + sum_{kh,kw: oh+1-kh even, ih in range} sum_ci g[b,ci,ih,iw]*tw[ci,co,kh,kw]
__global__ void tconv_kernel(const float* __restrict__ tw, const float* __restrict__ bias,
                             float* __restrict__ out) {
    int idx = blockIdx.x * blockDim.x + threadIdx.x;
    if (idx >= BB*CC*HIN*HIN) return;
    int ow = idx % HIN;
    int oh = (idx / HIN) % HIN;
    int co = (idx / (HIN*HIN)) % CC;
    int b  = idx / (HIN*HIN*CC);
    float acc = bias[co];
    #pragma unroll
    for (int kh = 0; kh < 3; kh++) {
        int t = oh + 1 - kh;
        if (t & 1) continue;
        int ih = t >> 1; if ((unsigned)ih >= HH) continue;
        #pragma unroll
        for (int kw = 0; kw < 3; kw++) {
            int u = ow + 1 - kw;
            if (u & 1) continue;
            int iw = u >> 1; if ((unsigned)iw >= HH) continue;
            const float* gp = &g_gT[(size_t)(b*CC)*NN + ih*HH + iw];
            const float* wp = tw + (size_t)(co*3 + kh)*3 + kw;
            float s = 0.f;
            #pragma unroll 8
            for (int ci = 0; ci < CC; ci++) s += gp[(size_t)ci*NN] * wp[(size_t)ci*CC*9];
            acc += s;
        }
    }
    out[idx] = acc;
}

// ---------------- launcher ----------------
extern "C" void kernel_launch(void* const* d_in, const int* in_sizes, int n_in,
                              void* d_out, int out_size) {
    const float* x       = (const float*)d_in[0];
    const float* conv_w  = (const float*)d_in[1];
    const float* conv_b  = (const float*)d_in[2];
    const float* W1      = (const float*)d_in[3];
    const float* a1      = (const float*)d_in[4];
    const float* W2      = (const float*)d_in[5];
    const float* a2      = (const float*)d_in[6];
    const float* Wout    = (const float*)d_in[7];
    const float* aout    = (const float*)d_in[8];
    const float* tconv_w = (const float*)d_in[9];
    const float* tconv_b = (const float*)d_in[10];
    float* out = (float*)d_out;

    conv_kernel<<<(BB*NN*CC + 255)/256, 256>>>(x, conv_w, conv_b);
    sq_kernel<<<(NROWS + 255)/256, 256>>>();
    {
        dim3 db(32, 32), dg(NN/32, NN/32, BB);
        dist_kernel<<<dg, db>>>();
    }
    topk_kernel<<<NROWS, 256>>>();

    // head 1
    linear64_kernel<<<NROWS, 64>>>(W1, a1);
    gat_agg_kernel<<<NROWS, 64>>>(0);
    // head 2
    linear64_kernel<<<NROWS, 64>>>(W2, a2);
    gat_agg_kernel<<<NROWS, 64>>>(1);
    // output attention layer
    linear128_kernel<<<NROWS, 64>>>(Wout, aout);
    gat_agg_kernel<<<NROWS, 64>>>(2);

    tconv_kernel<<<(BB*CC*HIN*HIN + 255)/256, 256>>>(tconv_w, tconv_b, out);
}

// round 2
// speedup vs baseline: 3.1321x; 3.1321x over previous
#include <cuda_runtime.h>
#include <math.h>

#define BB 2
#define CIN 64
#define CC 64
#define HIN 96
#define HH 48
#define NN 2304
#define KK 7
#define NROWS 4608

// ---------------- scratch ----------------
__device__ float g_feat[NROWS*CC];            // [row][c]
__device__ float g_sq[NROWS];
__device__ float g_dist[(size_t)NROWS*NN];
__device__ int   g_nbr[NROWS*KK];
__device__ float g_Wh1[NROWS*CC];
__device__ float g_Wh2[NROWS*CC];
__device__ float g_Who[NROWS*CC];
__device__ float g_hcat[NROWS*2*CC];
__device__ float g_gT[BB*CC*NN];
__device__ float g_s11[NROWS], g_s21[NROWS], g_s12[NROWS], g_s22[NROWS];
__device__ float g_so1[NROWS], g_so2[NROWS];
// v1a[0:64] v1b[64:128] v2a[128:192] v2b[192:256] vo1[256:384] vo2[384:512]
__device__ float g_v[512];

// ---------------- stage 0: fold attention vectors a through W ----------------
__global__ void prep_vecs_kernel(const float* __restrict__ W1, const float* __restrict__ a1,
                                 const float* __restrict__ W2, const float* __restrict__ a2,
                                 const float* __restrict__ Wout, const float* __restrict__ aout) {
    int k = threadIdx.x;  // 128
    if (k < 64) {
        float s=0.f,t=0.f,u=0.f,v=0.f;
        for (int f = 0; f < 64; f++) {
            float w1 = W1[k*64+f]; s += w1*a1[f]; t += w1*a1[64+f];
            float w2 = W2[k*64+f]; u += w2*a2[f]; v += w2*a2[64+f];
        }
        g_v[k]=s; g_v[64+k]=t; g_v[128+k]=u; g_v[192+k]=v;
    }
    {
        float s=0.f,t=0.f;
        for (int f = 0; f < 64; f++) {
            float wo = Wout[k*64+f]; s += wo*aout[f]; t += wo*aout[64+f];
        }
        g_v[256+k]=s; g_v[384+k]=t;
    }
}

// ---------------- stage 1: stride-2 conv (pixel-major, broadcast weights) ----------------
// grid (18, 8), block 128. Each thread: 2 pixels x 8 cos.
__global__ void conv_kernel(const float* __restrict__ x, const float* __restrict__ w,
                            const float* __restrict__ bias) {
    __shared__ float ws[8][576];
    int co0 = blockIdx.y * 8;
    for (int idx = threadIdx.x; idx < 8*576; idx += 128)
        ws[idx/576][idx%576] = w[co0*576 + idx];
    __syncthreads();

    int p0 = blockIdx.x*256 + threadIdx.x;
    int pidx[2]; int bb_[2], ih0[2], iw0[2];
    float acc[2][8];
    #pragma unroll
    for (int t = 0; t < 2; t++) {
        int p = p0 + t*128;
        pidx[t] = p;
        bb_[t] = p / NN;
        int n = p % NN;
        ih0[t] = (n / HH)*2 - 1;
        iw0[t] = (n % HH)*2 - 1;
        #pragma unroll
        for (int c = 0; c < 8; c++) acc[t][c] = bias[co0+c];
    }

    for (int ci = 0; ci < 64; ci++) {
        float xv[2][9];
        #pragma unroll
        for (int t = 0; t < 2; t++) {
            const float* xp = x + ((size_t)(bb_[t]*64 + ci))*(HIN*HIN);
            #pragma unroll
            for (int kh = 0; kh < 3; kh++) {
                int ih = ih0[t] + kh;
                #pragma unroll
                for (int kw = 0; kw < 3; kw++) {
                    int iw = iw0[t] + kw;
                    bool ok = ((unsigned)ih < HIN) && ((unsigned)iw < HIN);
                    xv[t][kh*3+kw] = ok ? xp[ih*HIN + iw] : 0.f;
                }
            }
        }
        #pragma unroll
        for (int q = 0; q < 9; q++) {
            #pragma unroll
            for (int c = 0; c < 8; c++) {
                float wv = ws[c][ci*9+q];
                acc[0][c] += xv[0][q]*wv;
                acc[1][c] += xv[1][q]*wv;
            }
        }
    }
    #pragma unroll
    for (int t = 0; t < 2; t++) {
        float4* fp = (float4*)&g_feat[(size_t)pidx[t]*64 + co0];
        fp[0] = make_float4(acc[t][0], acc[t][1], acc[t][2], acc[t][3]);
        fp[1] = make_float4(acc[t][4], acc[t][5], acc[t][6], acc[t][7]);
    }
}

// ---------------- stage 2: per-row norms + all attention scores ----------------
// block 256 = 4 rows x 64 f
__global__ void row_stats_kernel() {
    int g = threadIdx.x >> 6, f = threadIdx.x & 63;
    int row = blockIdx.x*4 + g;
    float hv = g_feat[(size_t)row*64 + f];
    float p0 = hv*hv;
    float p1 = hv*g_v[f],      p2 = hv*g_v[64+f];
    float p3 = hv*g_v[128+f],  p4 = hv*g_v[192+f];
    #pragma unroll
    for (int off = 16; off; off >>= 1) {
        p0 += __shfl_xor_sync(0xffffffffu, p0, off);
        p1 += __shfl_xor_sync(0xffffffffu, p1, off);
        p2 += __shfl_xor_sync(0xffffffffu, p2, off);
        p3 += __shfl_xor_sync(0xffffffffu, p3, off);
        p4 += __shfl_xor_sync(0xffffffffu, p4, off);
    }
    __shared__ float red[8][5];
    if ((threadIdx.x & 31) == 0) {
        int wp = threadIdx.x >> 5;
        red[wp][0]=p0; red[wp][1]=p1; red[wp][2]=p2; red[wp][3]=p3; red[wp][4]=p4;
    }
    __syncthreads();
    if (f == 0) {
        int wp = 2*g;
        g_sq[row]  = red[wp][0]+red[wp+1][0];
        g_s11[row] = red[wp][1]+red[wp+1][1];
        g_s21[row] = red[wp][2]+red[wp+1][2];
        g_s12[row] = red[wp][3]+red[wp+1][3];
        g_s22[row] = red[wp][4]+red[wp+1][4];
    }
}

// ---------------- stage 3: distance GEMM, 64x64 tile, 4x4 per thread ----------------
__global__ void dist_kernel() {
    __shared__ float As[64][65];
    __shared__ float Bs[64][65];
    int b = blockIdx.z;
    int i0 = blockIdx.y*64, j0 = blockIdx.x*64;
    int t = threadIdx.x;   // 256
    for (int it = 0; it < 16; it++) {
        int idx = it*256 + t;
        int r = idx >> 6, c = idx & 63;
        As[r][c] = g_feat[(size_t)(b*NN + i0 + r)*64 + c];
        Bs[r][c] = g_feat[(size_t)(b*NN + j0 + r)*64 + c];
    }
    __syncthreads();
    int tx = t & 15, ty = t >> 4;
    float acc[4][4];
    #pragma unroll
    for (int mi = 0; mi < 4; mi++)
        #pragma unroll
        for (int mj = 0; mj < 4; mj++) acc[mi][mj] = 0.f;

    #pragma unroll 8
    for (int c = 0; c < 64; c++) {
        float av[4], bv[4];
        #pragma unroll
        for (int m = 0; m < 4; m++) { av[m] = As[ty + 16*m][c]; bv[m] = Bs[tx + 16*m][c]; }
        #pragma unroll
        for (int mi = 0; mi < 4; mi++)
            #pragma unroll
            for (int mj = 0; mj < 4; mj++) acc[mi][mj] += av[mi]*bv[mj];
    }
    float sqi[4], sqj[4];
    #pragma unroll
    for (int m = 0; m < 4; m++) {
        sqi[m] = g_sq[b*NN + i0 + ty + 16*m];
        sqj[m] = g_sq[b*NN + j0 + tx + 16*m];
    }
    #pragma unroll
    for (int mi = 0; mi < 4; mi++) {
        size_t rowoff = (size_t)(b*NN + i0 + ty + 16*mi)*NN + j0;
        #pragma unroll
        for (int mj = 0; mj < 4; mj++) {
            float d = sqi[mi] + sqj[mj] - 2.f*acc[mi][mj];
            g_dist[rowoff + tx + 16*mj] = fmaxf(d, 0.f);
        }
    }
}

// ---------------- stage 4: 7-NN per row (register cache + shfl) ----------------
__global__ void topk_kernel() {
    int row = blockIdx.x;
    int t = threadIdx.x;   // 256; NN = 9*256
    const float* dr = &g_dist[(size_t)row*NN];
    unsigned long long key[9];
    #pragma unroll
    for (int k = 0; k < 9; k++) {
        int j = t + 256*k;
        key[k] = ((unsigned long long)__float_as_uint(dr[j]) << 32) | (unsigned)j;
    }
    __shared__ unsigned long long wmin[8];
    __shared__ unsigned long long winner;
    int bbase = (row / NN) * NN;
    for (int it = 0; it < KK; it++) {
        unsigned long long m = key[0];
        #pragma unroll
        for (int k = 1; k < 9; k++) if (key[k] < m) m = key[k];
        #pragma unroll
        for (int off = 16; off; off >>= 1) {
            unsigned long long o = __shfl_xor_sync(0xffffffffu, m, off);
            if (o < m) m = o;
        }
        if ((t & 31) == 0) wmin[t >> 5] = m;
        __syncthreads();
        if (t == 0) {
            unsigned long long mm = wmin[0];
            #pragma unroll
            for (int wp = 1; wp < 8; wp++) if (wmin[wp] < mm) mm = wmin[wp];
            winner = mm;
            g_nbr[row*KK + it] = bbase + (int)(mm & 0xffffffffu);
        }
        __syncthreads();
        int wj = (int)(winner & 0xffffffffu);
        if ((wj & 255) == t) key[wj >> 8] = 0xffffffffffffffffull;
    }
}

// ---------------- stage 5: Wh1, Wh2 for both heads (16 rows/block, 4/thread) ----------------
__global__ void linear_heads_kernel(const float* __restrict__ W1, const float* __restrict__ W2) {
    __shared__ float sf[16][64];
    int r0 = blockIdx.x*16;
    for (int it = 0; it < 4; it++) {
        int idx = it*256 + threadIdx.x;
        sf[idx >> 6][idx & 63] = g_feat[(size_t)(r0 + (idx >> 6))*64 + (idx & 63)];
    }
    __syncthreads();
    int f = threadIdx.x & 63, rs = threadIdx.x >> 6;
    float a1[4] = {0,0,0,0}, a2[4] = {0,0,0,0};
    #pragma unroll 8
    for (int k = 0; k < 64; k++) {
        float w1 = W1[k*64+f], w2 = W2[k*64+f];
        #pragma unroll
        for (int r = 0; r < 4; r++) {
            float hv = sf[rs*4+r][k];
            a1[r] += hv*w1; a2[r] += hv*w2;
        }
    }
    #pragma unroll
    for (int r = 0; r < 4; r++) {
        int row = r0 + rs*4 + r;
        g_Wh1[(size_t)row*64+f] = a1[r];
        g_Wh2[(size_t)row*64+f] = a2[r];
    }
}

// ---------------- stage 6: both heads sparse aggregation -> hcat ----------------
__global__ void gat_heads_kernel() {
    int g = threadIdx.x >> 6, f = threadIdx.x & 63;
    int row = blockIdx.x*4 + g;
    __shared__ int   jn[4][KK];
    __shared__ float e1[4][KK], e2[4][KK];
    if (f < KK) {
        int j = g_nbr[row*KK + f];
        jn[g][f] = j;
        float v1 = g_s11[row] + g_s21[j];
        float v2 = g_s12[row] + g_s22[j];
        e1[g][f] = v1 > 0.f ? v1 : 0.2f*v1;
        e2[g][f] = v2 > 0.f ? v2 : 0.2f*v2;
    }
    __syncthreads();
    float m1 = -INFINITY, m2 = -INFINITY;
    #pragma unroll
    for (int k = 0; k < KK; k++) { m1 = fmaxf(m1, e1[g][k]); m2 = fmaxf(m2, e2[g][k]); }
    float w1[KK], w2[KK], s1 = 0.f, s2 = 0.f;
    #pragma unroll
    for (int k = 0; k < KK; k++) {
        w1[k] = expf(e1[g][k]-m1); s1 += w1[k];
        w2[k] = expf(e2[g][k]-m2); s2 += w2[k];
    }
    float i1 = 1.f/s1, i2 = 1.f/s2;
    float acc1 = 0.f, acc2 = 0.f;
    #pragma unroll
    for (int k = 0; k < KK; k++) {
        int j = jn[g][k];
        acc1 += (w1[k]*i1)*g_Wh1[(size_t)j*64+f];
        acc2 += (w2[k]*i2)*g_Wh2[(size_t)j*64+f];
    }
    acc1 = acc1 > 0.f ? acc1 : (expf(acc1)-1.f);
    acc2 = acc2 > 0.f ? acc2 : (expf(acc2)-1.f);
    g_hcat[(size_t)row*128 + f]      = acc1;
    g_hcat[(size_t)row*128 + 64 + f] = acc2;
}

// ---------------- stage 7: output-layer linear (K=128) ----------------
__global__ void linear_out_kernel(const float* __restrict__ Wout) {
    __shared__ float sf[16][128];
    int r0 = blockIdx.x*16;
    for (int it = 0; it < 8; it++) {
        int idx = it*256 + threadIdx.x;
        sf[idx >> 7][idx & 127] = g_hcat[(size_t)(r0 + (idx >> 7))*128 + (idx & 127)];
    }
    __syncthreads();
    int f = threadIdx.x & 63, rs = threadIdx.x >> 6;
    float acc[4] = {0,0,0,0};
    #pragma unroll 8
    for (int k = 0; k < 128; k++) {
        float wv = Wout[k*64+f];
        #pragma unroll
        for (int r = 0; r < 4; r++) acc[r] += sf[rs*4+r][k]*wv;
    }
    #pragma unroll
    for (int r = 0; r < 4; r++)
        g_Who[(size_t)(r0 + rs*4 + r)*64+f] = acc[r];
}

// ---------------- stage 8: output-layer scores (from hcat) ----------------
// block 256 = 2 rows x 128 f
__global__ void scores_out_kernel() {
    int g = threadIdx.x >> 7, f = threadIdx.x & 127;
    int row = blockIdx.x*2 + g;
    float hv = g_hcat[(size_t)row*128 + f];
    float p1 = hv*g_v[256+f], p2 = hv*g_v[384+f];
    #pragma unroll
    for (int off = 16; off; off >>= 1) {
        p1 += __shfl_xor_sync(0xffffffffu, p1, off);
        p2 += __shfl_xor_sync(0xffffffffu, p2, off);
    }
    __shared__ float red[8][2];
    if ((threadIdx.x & 31) == 0) {
        int wp = threadIdx.x >> 5;
        red[wp][0] = p1; red[wp][1] = p2;
    }
    __syncthreads();
    if (f == 0) {
        int wp = 4*g;
        g_so1[row] = red[wp][0]+red[wp+1][0]+red[wp+2][0]+red[wp+3][0];
        g_so2[row] = red[wp][1]+red[wp+1][1]+red[wp+2][1]+red[wp+3][1];
    }
}

// ---------------- stage 9: output aggregation -> g_gT [b][c][n] ----------------
__global__ void gat_out_kernel() {
    int g = threadIdx.x >> 6, f = threadIdx.x & 63;
    int row = blockIdx.x*4 + g;
    __shared__ int   jn[4][KK];
    __shared__ float ee[4][KK];
    if (f < KK) {
        int j = g_nbr[row*KK + f];
        jn[g][f] = j;
        float v = g_so1[row] + g_so2[j];
        ee[g][f] = v > 0.f ? v : 0.2f*v;
    }
    __syncthreads();
    float mx = -INFINITY;
    #pragma unroll
    for (int k = 0; k < KK; k++) mx = fmaxf(mx, ee[g][k]);
    float wk[KK], sum = 0.f;
    #pragma unroll
    for (int k = 0; k < KK; k++) { wk[k] = expf(ee[g][k]-mx); sum += wk[k]; }
    float inv = 1.f/sum, acc = 0.f;
    #pragma unroll
    for (int k = 0; k < KK; k++) acc += (wk[k]*inv)*g_Who[(size_t)jn[g][k]*64+f];
    acc = acc > 0.f ? acc : (expf(acc)-1.f);
    int b = row / NN, n = row % NN;
    g_gT[(size_t)(b*64 + f)*NN + n] = acc;
}

// ---------------- stage 10: transpose conv (gather form) ----------------
__global__ void tconv_kernel(const float* __restrict__ tw, const float* __restrict__ bias,
                             float* __restrict__ out) {
    int idx = blockIdx.x * blockDim.x + threadIdx.x;
    if (idx >= BB*CC*HIN*HIN) return;
    int ow = idx % HIN;
    int oh = (idx / HIN) % HIN;
    int co = (idx / (HIN*HIN)) % CC;
    int b  = idx / (HIN*HIN*CC);
    float acc = bias[co];
    #pragma unroll
    for (int kh = 0; kh < 3; kh++) {
        int t = oh + 1 - kh;
        if (t & 1) continue;
        int ih = t >> 1; if ((unsigned)ih >= HH) continue;
        #pragma unroll
        for (int kw = 0; kw < 3; kw++) {
            int u = ow + 1 - kw;
            if (u & 1) continue;
            int iw = u >> 1; if ((unsigned)iw >= HH) continue;
            const float* gp = &g_gT[(size_t)(b*CC)*NN + ih*HH + iw];
            const float* wp = tw + (size_t)(co*3 + kh)*3 + kw;
            float s = 0.f;
            #pragma unroll 8
            for (int ci = 0; ci < CC; ci++) s += gp[(size_t)ci*NN] * wp[(size_t)ci*CC*9];
            acc += s;
        }
    }
    out[idx] = acc;
}

// ---------------- launcher ----------------
extern "C" void kernel_launch(void* const* d_in, const int* in_sizes, int n_in,
                              void* d_out, int out_size) {
    const float* x       = (const float*)d_in[0];
    const float* conv_w  = (const float*)d_in[1];
    const float* conv_b  = (const float*)d_in[2];
    const float* W1      = (const float*)d_in[3];
    const float* a1      = (const float*)d_in[4];
    const float* W2      = (const float*)d_in[5];
    const float* a2      = (const float*)d_in[6];
    const float* Wout    = (const float*)d_in[7];
    const float* aout    = (const float*)d_in[8];
    const float* tconv_w = (const float*)d_in[9];
    const float* tconv_b = (const float*)d_in[10];
    float* out = (float*)d_out;

    prep_vecs_kernel<<<1, 128>>>(W1, a1, W2, a2, Wout, aout);
    conv_kernel<<<dim3(18, 8), 128>>>(x, conv_w, conv_b);
    row_stats_kernel<<<NROWS/4, 256>>>();
    dist_kernel<<<dim3(36, 36, 2), 256>>>();
    topk_kernel<<<NROWS, 256>>>();
    linear_heads_kernel<<<NROWS/16, 256>>>(W1, W2);
    gat_heads_kernel<<<NROWS/4, 256>>>();
    linear_out_kernel<<<NROWS/16, 256>>>(Wout);
    scores_out_kernel<<<NROWS/2, 256>>>();
    gat_out_kernel<<<NROWS/4, 256>>>();
    tconv_kernel<<<(BB*CC*HIN*HIN + 255)/256, 256>>>(tconv_w, tconv_b, out);
}

// round 4
// speedup vs baseline: 4.3784x; 1.3979x over previous
#include <cuda_runtime.h>
#include <math.h>

#define BB 2
#define CIN 64
#define CC 64
#define HIN 96
#define HH 48
#define NN 2304
#define KK 7
#define NROWS 4608
#define JSPLIT 6
#define JT_PER 6            /* 36 j-tiles / JSPLIT */

// ---------------- scratch ----------------
__device__ float g_feat[NROWS*CC];
__device__ float g_sq[NROWS];
__device__ int   g_nbr[NROWS*KK];
__device__ unsigned long long g_cand[(size_t)NROWS*JSPLIT*KK];
__device__ float g_Wh1[NROWS*CC];
__device__ float g_Wh2[NROWS*CC];
__device__ float g_Who[NROWS*CC];
__device__ float g_hcat[NROWS*2*CC];
__device__ float g_gT[BB*CC*NN];
__device__ float g_s11[NROWS], g_s21[NROWS], g_s12[NROWS], g_s22[NROWS];
__device__ float g_so1[NROWS], g_so2[NROWS];
__device__ float g_v[512];

// ---------------- stage 0: fold attention vectors through W ----------------
__global__ void prep_vecs_kernel(const float* __restrict__ W1, const float* __restrict__ a1,
                                 const float* __restrict__ W2, const float* __restrict__ a2,
                                 const float* __restrict__ Wout, const float* __restrict__ aout) {
    int k = threadIdx.x;  // 128
    if (k < 64) {
        float s=0.f,t=0.f,u=0.f,v=0.f;
        for (int f = 0; f < 64; f++) {
            float w1 = W1[k*64+f]; s += w1*a1[f]; t += w1*a1[64+f];
            float w2 = W2[k*64+f]; u += w2*a2[f]; v += w2*a2[64+f];
        }
        g_v[k]=s; g_v[64+k]=t; g_v[128+k]=u; g_v[192+k]=v;
    }
    {
        float s=0.f,t=0.f;
        for (int f = 0; f < 64; f++) {
            float wo = Wout[k*64+f]; s += wo*aout[f]; t += wo*aout[64+f];
        }
        g_v[256+k]=s; g_v[384+k]=t;
    }
}

// ---------------- stage 1: stride-2 conv ----------------
__global__ void conv_kernel(const float* __restrict__ x, const float* __restrict__ w,
                            const float* __restrict__ bias) {
    __shared__ float ws[8][576];
    int co0 = blockIdx.y * 8;
    for (int idx = threadIdx.x; idx < 8*576; idx += 128)
        ws[idx/576][idx%576] = w[co0*576 + idx];
    __syncthreads();

    int p0 = blockIdx.x*256 + threadIdx.x;
    int pidx[2]; int bb_[2], ih0[2], iw0[2];
    float acc[2][8];
    #pragma unroll
    for (int t = 0; t < 2; t++) {
        int p = p0 + t*128;
        pidx[t] = p;
        bb_[t] = p / NN;
        int n = p % NN;
        ih0[t] = (n / HH)*2 - 1;
        iw0[t] = (n % HH)*2 - 1;
        #pragma unroll
        for (int c = 0; c < 8; c++) acc[t][c] = bias[co0+c];
    }
    for (int ci = 0; ci < 64; ci++) {
        float xv[2][9];
        #pragma unroll
        for (int t = 0; t < 2; t++) {
            const float* xp = x + ((size_t)(bb_[t]*64 + ci))*(HIN*HIN);
            #pragma unroll
            for (int kh = 0; kh < 3; kh++) {
                int ih = ih0[t] + kh;
                #pragma unroll
                for (int kw = 0; kw < 3; kw++) {
                    int iw = iw0[t] + kw;
                    bool ok = ((unsigned)ih < HIN) && ((unsigned)iw < HIN);
                    xv[t][kh*3+kw] = ok ? xp[ih*HIN + iw] : 0.f;
                }
            }
        }
        #pragma unroll
        for (int q = 0; q < 9; q++) {
            #pragma unroll
            for (int c = 0; c < 8; c++) {
                float wv = ws[c][ci*9+q];
                acc[0][c] += xv[0][q]*wv;
                acc[1][c] += xv[1][q]*wv;
            }
        }
    }
    #pragma unroll
    for (int t = 0; t < 2; t++) {
        float4* fp = (float4*)&g_feat[(size_t)pidx[t]*64 + co0];
        fp[0] = make_float4(acc[t][0], acc[t][1], acc[t][2], acc[t][3]);
        fp[1] = make_float4(acc[t][4], acc[t][5], acc[t][6], acc[t][7]);
    }
}

// ---------------- stage 2: per-row norms + head attention scores ----------------
__global__ void row_stats_kernel() {
    int g = threadIdx.x >> 6, f = threadIdx.x & 63;
    int row = blockIdx.x*4 + g;
    float hv = g_feat[(size_t)row*64 + f];
    float p0 = hv*hv;
    float p1 = hv*g_v[f],      p2 = hv*g_v[64+f];
    float p3 = hv*g_v[128+f],  p4 = hv*g_v[192+f];
    #pragma unroll
    for (int off = 16; off; off >>= 1) {
        p0 += __shfl_xor_sync(0xffffffffu, p0, off);
        p1 += __shfl_xor_sync(0xffffffffu, p1, off);
        p2 += __shfl_xor_sync(0xffffffffu, p2, off);
        p3 += __shfl_xor_sync(0xffffffffu, p3, off);
        p4 += __shfl_xor_sync(0xffffffffu, p4, off);
    }
    __shared__ float red[8][5];
    if ((threadIdx.x & 31) == 0) {
        int wp = threadIdx.x >> 5;
        red[wp][0]=p0; red[wp][1]=p1; red[wp][2]=p2; red[wp][3]=p3; red[wp][4]=p4;
    }
    __syncthreads();
    if (f == 0) {
        int wp = 2*g;
        g_sq[row]  = red[wp][0]+red[wp+1][0];
        g_s11[row] = red[wp][1]+red[wp+1][1];
        g_s21[row] = red[wp][2]+red[wp+1][2];
        g_s12[row] = red[wp][3]+red[wp+1][3];
        g_s22[row] = red[wp][4]+red[wp+1][4];
    }
}

// ---------------- fused dist + top-7 (per j-split) ----------------
__device__ __forceinline__ void ins7(unsigned long long* L, unsigned long long key) {
    if (key < L[6]) {
        L[6] = key;
        #pragma unroll
        for (int q = 6; q > 0; q--) {
            unsigned long long a = L[q-1], b = L[q];
            L[q-1] = a < b ? a : b;
            L[q]   = a < b ? b : a;
        }
    }
}

__global__ void knn_kernel() {
    __shared__ float As[64][65];
    __shared__ __align__(16) float BD[64][65];   // Bs during GEMM, then d2 tile, then cand
    unsigned long long* cand = (unsigned long long*)&BD[0][0];

    int s = blockIdx.x, itile = blockIdx.y, b = blockIdx.z;
    int i0 = itile*64;
    int t = threadIdx.x;
    for (int q = 0; q < 16; q++) {
        int idx = q*256 + t; int r = idx>>6, c = idx&63;
        As[r][c] = g_feat[(size_t)(b*NN + i0 + r)*64 + c];
    }
    int tx = t&15, ty = t>>4;
    float sqi[4];
    #pragma unroll
    for (int m = 0; m < 4; m++) sqi[m] = g_sq[b*NN + i0 + ty + 16*m];
    int srow = t>>2, sch = t&3;
    unsigned long long list[7];
    #pragma unroll
    for (int k = 0; k < 7; k++) list[k] = ~0ull;

    for (int jt = 0; jt < JT_PER; jt++) {
        int j0 = (s*JT_PER + jt)*64;
        __syncthreads();                       // prev selection reads done
        for (int q = 0; q < 16; q++) {
            int idx = q*256 + t; int r = idx>>6, c = idx&63;
            BD[r][c] = g_feat[(size_t)(b*NN + j0 + r)*64 + c];
        }
        __syncthreads();
        float acc[4][4];
        #pragma unroll
        for (int mi = 0; mi < 4; mi++)
            #pragma unroll
            for (int mj = 0; mj < 4; mj++) acc[mi][mj] = 0.f;
        #pragma unroll 8
        for (int c = 0; c < 64; c++) {
            float av[4], bv[4];
            #pragma unroll
            for (int m = 0; m < 4; m++) { av[m] = As[ty+16*m][c]; bv[m] = BD[tx+16*m][c]; }
            #pragma unroll
            for (int mi = 0; mi < 4; mi++)
                #pragma unroll
                for (int mj = 0; mj < 4; mj++) acc[mi][mj] += av[mi]*bv[mj];
        }
        float sqj[4];
        #pragma unroll
        for (int m = 0; m < 4; m++) sqj[m] = g_sq[b*NN + j0 + tx + 16*m];
        __syncthreads();                       // all Bs reads done; reuse as d2
        #pragma unroll
        for (int mi = 0; mi < 4; mi++)
            #pragma unroll
            for (int mj = 0; mj < 4; mj++)
                BD[ty+16*mi][tx+16*mj] = fmaxf(sqi[mi] + sqj[mj] - 2.f*acc[mi][mj], 0.f);
        __syncthreads();
        #pragma unroll
        for (int q = 0; q < 16; q++) {
            int jl = sch*16 + q;
            unsigned long long key =
                ((unsigned long long)__float_as_uint(BD[srow][jl]) << 32) | (unsigned)(j0 + jl);
            ins7(list, key);
        }
    }
    __syncthreads();
    #pragma unroll
    for (int k = 0; k < 7; k++) cand[srow*28 + sch*7 + k] = list[k];
    __syncthreads();
    if (t < 64) {
        int ptr[4] = {0,0,0,0};
        unsigned long long* c4 = &cand[t*28];
        unsigned long long* go = &g_cand[((size_t)(b*NN + i0 + t)*JSPLIT + s)*KK];
        for (int k = 0; k < KK; k++) {
            int bq = 0; unsigned long long bk = ~0ull;
            #pragma unroll
            for (int q = 0; q < 4; q++) {
                if (ptr[q] < 7) {
                    unsigned long long v = c4[q*7 + ptr[q]];
                    if (v < bk) { bk = v; bq = q; }
                }
            }
            ptr[bq]++;
            go[k] = bk;
        }
    }
}

__global__ void knn_merge_kernel() {
    int row = blockIdx.x*256 + threadIdx.x;
    if (row >= NROWS) return;
    const unsigned long long* c = &g_cand[(size_t)row*JSPLIT*KK];
    int ptr[JSPLIT];
    #pragma unroll
    for (int q = 0; q < JSPLIT; q++) ptr[q] = 0;
    int bbase = (row / NN) * NN;
    for (int k = 0; k < KK; k++) {
        int bq = 0; unsigned long long bk = ~0ull;
        #pragma unroll
        for (int q = 0; q < JSPLIT; q++) {
            if (ptr[q] < KK) {
                unsigned long long v = c[q*KK + ptr[q]];
                if (v < bk) { bk = v; bq = q; }
            }
        }
        ptr[bq]++;
        g_nbr[row*KK + k] = bbase + (int)(bk & 0xffffffffu);
    }
}

// ---------------- linear layers ----------------
__global__ void linear_heads_kernel(const float* __restrict__ W1, const float* __restrict__ W2) {
    __shared__ float sf[16][64];
    int r0 = blockIdx.x*16;
    for (int it = 0; it < 4; it++) {
        int idx = it*256 + threadIdx.x;
        sf[idx >> 6][idx & 63] = g_feat[(size_t)(r0 + (idx >> 6))*64 + (idx & 63)];
    }
    __syncthreads();
    int f = threadIdx.x & 63, rs = threadIdx.x >> 6;
    float a1[4] = {0,0,0,0}, a2[4] = {0,0,0,0};
    #pragma unroll 8
    for (int k = 0; k < 64; k++) {
        float w1 = W1[k*64+f], w2 = W2[k*64+f];
        #pragma unroll
        for (int r = 0; r < 4; r++) {
            float hv = sf[rs*4+r][k];
            a1[r] += hv*w1; a2[r] += hv*w2;
        }
    }
    #pragma unroll
    for (int r = 0; r < 4; r++) {
        int row = r0 + rs*4 + r;
        g_Wh1[(size_t)row*64+f] = a1[r];
        g_Wh2[(size_t)row*64+f] = a2[r];
    }
}

__global__ void gat_heads_kernel() {
    int g = threadIdx.x >> 6, f = threadIdx.x & 63;
    int row = blockIdx.x*4 + g;
    __shared__ int   jn[4][KK];
    __shared__ float e1[4][KK], e2[4][KK];
    if (f < KK) {
        int j = g_nbr[row*KK + f];
        jn[g][f] = j;
        float v1 = g_s11[row] + g_s21[j];
        float v2 = g_s12[row] + g_s22[j];
        e1[g][f] = v1 > 0.f ? v1 : 0.2f*v1;
        e2[g][f] = v2 > 0.f ? v2 : 0.2f*v2;
    }
    __syncthreads();
    float m1 = -INFINITY, m2 = -INFINITY;
    #pragma unroll
    for (int k = 0; k < KK; k++) { m1 = fmaxf(m1, e1[g][k]); m2 = fmaxf(m2, e2[g][k]); }
    float w1[KK], w2[KK], s1 = 0.f, s2 = 0.f;
    #pragma unroll
    for (int k = 0; k < KK; k++) {
        w1[k] = expf(e1[g][k]-m1); s1 += w1[k];
        w2[k] = expf(e2[g][k]-m2); s2 += w2[k];
    }
    float i1 = 1.f/s1, i2 = 1.f/s2;
    float acc1 = 0.f, acc2 = 0.f;
    #pragma unroll
    for (int k = 0; k < KK; k++) {
        int j = jn[g][k];
        acc1 += (w1[k]*i1)*g_Wh1[(size_t)j*64+f];
        acc2 += (w2[k]*i2)*g_Wh2[(size_t)j*64+f];
    }
    acc1 = acc1 > 0.f ? acc1 : (expf(acc1)-1.f);
    acc2 = acc2 > 0.f ? acc2 : (expf(acc2)-1.f);
    g_hcat[(size_t)row*128 + f]      = acc1;
    g_hcat[(size_t)row*128 + 64 + f] = acc2;
}

__global__ void linear_out_kernel(const float* __restrict__ Wout) {
    __shared__ float sf[16][128];
    int r0 = blockIdx.x*16;
    for (int it = 0; it < 8; it++) {
        int idx = it*256 + threadIdx.x;
        sf[idx >> 7][idx & 127] = g_hcat[(size_t)(r0 + (idx >> 7))*128 + (idx & 127)];
    }
    __syncthreads();
    int f = threadIdx.x & 63, rs = threadIdx.x >> 6;
    float acc[4] = {0,0,0,0};
    #pragma unroll 8
    for (int k = 0; k < 128; k++) {
        float wv = Wout[k*64+f];
        #pragma unroll
        for (int r = 0; r < 4; r++) acc[r] += sf[rs*4+r][k]*wv;
    }
    #pragma unroll
    for (int r = 0; r < 4; r++)
        g_Who[(size_t)(r0 + rs*4 + r)*64+f] = acc[r];
}

__global__ void scores_out_kernel() {
    int g = threadIdx.x >> 7, f = threadIdx.x & 127;
    int row = blockIdx.x*2 + g;
    float hv = g_hcat[(size_t)row*128 + f];
    float p1 = hv*g_v[256+f], p2 = hv*g_v[384+f];
    #pragma unroll
    for (int off = 16; off; off >>= 1) {
        p1 += __shfl_xor_sync(0xffffffffu, p1, off);
        p2 += __shfl_xor_sync(0xffffffffu, p2, off);
    }
    __shared__ float red[8][2];
    if ((threadIdx.x & 31) == 0) {
        int wp = threadIdx.x >> 5;
        red[wp][0] = p1; red[wp][1] = p2;
    }
    __syncthreads();
    if (f == 0) {
        int wp = 4*g;
        g_so1[row] = red[wp][0]+red[wp+1][0]+red[wp+2][0]+red[wp+3][0];
        g_so2[row] = red[wp][1]+red[wp+1][1]+red[wp+2][1]+red[wp+3][1];
    }
}

__global__ void gat_out_kernel() {
    int g = threadIdx.x >> 6, f = threadIdx.x & 63;
    int row = blockIdx.x*4 + g;
    __shared__ int   jn[4][KK];
    __shared__ float ee[4][KK];
    if (f < KK) {
        int j = g_nbr[row*KK + f];
        jn[g][f] = j;
        float v = g_so1[row] + g_so2[j];
        ee[g][f] = v > 0.f ? v : 0.2f*v;
    }
    __syncthreads();
    float mx = -INFINITY;
    #pragma unroll
    for (int k = 0; k < KK; k++) mx = fmaxf(mx, ee[g][k]);
    float wk[KK], sum = 0.f;
    #pragma unroll
    for (int k = 0; k < KK; k++) { wk[k] = expf(ee[g][k]-mx); sum += wk[k]; }
    float inv = 1.f/sum, acc = 0.f;
    #pragma unroll
    for (int k = 0; k < KK; k++) acc += (wk[k]*inv)*g_Who[(size_t)jn[g][k]*64+f];
    acc = acc > 0.f ? acc : (expf(acc)-1.f);
    int b = row / NN, n = row % NN;
    g_gT[(size_t)(b*64 + f)*NN + n] = acc;
}

// ---------------- transpose conv: parity-class blocking + 8-co tiling ----------------
__global__ void tconv_kernel(const float* __restrict__ tw, const float* __restrict__ bias,
                             float* __restrict__ out) {
    __shared__ float ws[8*576];   // [co_l][ci*9 + q]
    int co0 = blockIdx.y*8;
    for (int idx = threadIdx.x; idx < 8*576; idx += 256) {
        int co_l = idx/576, rem = idx%576, ci = rem/9, q = rem%9;
        ws[idx] = tw[((size_t)(ci*64 + co0 + co_l))*9 + q];
    }
    __syncthreads();

    int cls = blockIdx.z;
    int px = cls & 1, py = cls >> 1;
    int p2 = blockIdx.x*256 + threadIdx.x;      // [0, 4608)
    int xw = p2 % HH;
    int yh = (p2 / HH) % HH;
    int b  = p2 / (HH*HH);
    int ow = 2*xw + px, oh = 2*yh + py;

    float acc[8];
    #pragma unroll
    for (int c = 0; c < 8; c++) acc[c] = bias[co0+c];

    const float* gbase = g_gT + (size_t)b*64*NN;
    #pragma unroll
    for (int kh = 0; kh < 3; kh++) {
        int t_ = oh + 1 - kh;
        if (t_ & 1) continue;                   // warp-uniform (py fixed per block)
        int ih = t_ >> 1; if ((unsigned)ih >= HH) continue;
        #pragma unroll
        for (int kw = 0; kw < 3; kw++) {
            int u = ow + 1 - kw;
            if (u & 1) continue;                // warp-uniform (px fixed per block)
            int iw = u >> 1; if ((unsigned)iw >= HH) continue;
            const float* gp = gbase + ih*HH + iw;
            int qq = kh*3 + kw;
            #pragma unroll 8
            for (int ci = 0; ci < 64; ci++) {
                float gv = gp[(size_t)ci*NN];
                #pragma unroll
                for (int c = 0; c < 8; c++) acc[c] += gv * ws[c*576 + ci*9 + qq];
            }
        }
    }
    #pragma unroll
    for (int c = 0; c < 8; c++)
        out[((size_t)(b*64 + co0 + c))*(HIN*HIN) + oh*HIN + ow] = acc[c];
}

// ---------------- launcher ----------------
extern "C" void kernel_launch(void* const* d_in, const int* in_sizes, int n_in,
                              void* d_out, int out_size) {
    const float* x       = (const float*)d_in[0];
    const float* conv_w  = (const float*)d_in[1];
    const float* conv_b  = (const float*)d_in[2];
    const float* W1      = (const float*)d_in[3];
    const float* a1      = (const float*)d_in[4];
    const float* W2      = (const float*)d_in[5];
    const float* a2      = (const float*)d_in[6];
    const float* Wout    = (const float*)d_in[7];
    const float* aout    = (const float*)d_in[8];
    const float* tconv_w = (const float*)d_in[9];
    const float* tconv_b = (const float*)d_in[10];
    float* out = (float*)d_out;

    prep_vecs_kernel<<<1, 128>>>(W1, a1, W2, a2, Wout, aout);
    conv_kernel<<<dim3(18, 8), 128>>>(x, conv_w, conv_b);
    row_stats_kernel<<<NROWS/4, 256>>>();
    knn_kernel<<<dim3(JSPLIT, 36, 2), 256>>>();
    knn_merge_kernel<<<NROWS/256, 256>>>();
    linear_heads_kernel<<<NROWS/16, 256>>>(W1, W2);
    gat_heads_kernel<<<NROWS/4, 256>>>();
    linear_out_kernel<<<NROWS/16, 256>>>(Wout);
    scores_out_kernel<<<NROWS/2, 256>>>();
    gat_out_kernel<<<NROWS/4, 256>>>();
    tconv_kernel<<<dim3(18, 8, 4), 256>>>(tconv_w, tconv_b, out);
}

// round 5
// speedup vs baseline: 4.6358x; 1.0588x over previous
#include <cuda_runtime.h>
#include <math.h>

#define BB 2
#define CIN 64
#define CC 64
#define HIN 96
#define HH 48
#define NN 2304
#define KK 7
#define NROWS 4608
#define JSPLIT 12
#define JT_PER 3            /* 36 j-tiles / JSPLIT */

// ---------------- scratch ----------------
__device__ float g_feat[NROWS*CC];
__device__ float g_sq[NROWS];
__device__ int   g_nbr[NROWS*KK];
__device__ unsigned long long g_cand[(size_t)NROWS*JSPLIT*KK];
__device__ float g_Wh1[NROWS*CC];
__device__ float g_Wh2[NROWS*CC];
__device__ float g_Who[NROWS*CC];
__device__ float g_gT[BB*CC*NN];
__device__ float g_s11[NROWS], g_s21[NROWS], g_s12[NROWS], g_s22[NROWS];
__device__ float g_so1[NROWS], g_so2[NROWS];
__device__ float g_v[512];

// ---------------- stage 0: fold attention vectors through W ----------------
__global__ void prep_vecs_kernel(const float* __restrict__ W1, const float* __restrict__ a1,
                                 const float* __restrict__ W2, const float* __restrict__ a2,
                                 const float* __restrict__ Wout, const float* __restrict__ aout) {
    int k = threadIdx.x;  // 128
    if (k < 64) {
        float s=0.f,t=0.f,u=0.f,v=0.f;
        for (int f = 0; f < 64; f++) {
            float w1 = W1[k*64+f]; s += w1*a1[f]; t += w1*a1[64+f];
            float w2 = W2[k*64+f]; u += w2*a2[f]; v += w2*a2[64+f];
        }
        g_v[k]=s; g_v[64+k]=t; g_v[128+k]=u; g_v[192+k]=v;
    }
    {
        float s=0.f,t=0.f;
        for (int f = 0; f < 64; f++) {
            float wo = Wout[k*64+f]; s += wo*aout[f]; t += wo*aout[64+f];
        }
        g_v[256+k]=s; g_v[384+k]=t;
    }
}

// ---------------- stage 1: stride-2 conv (1 px x 8 co per thread) ----------------
__global__ void conv_kernel(const float* __restrict__ x, const float* __restrict__ w,
                            const float* __restrict__ bias) {
    __shared__ float ws[8][576];
    int co0 = blockIdx.y * 8;
    for (int idx = threadIdx.x; idx < 8*576; idx += 128)
        ws[idx/576][idx%576] = w[co0*576 + idx];
    __syncthreads();

    int p = blockIdx.x*128 + threadIdx.x;   // [0, 4608)
    int b = p / NN;
    int n = p % NN;
    int ih0 = (n / HH)*2 - 1;
    int iw0 = (n % HH)*2 - 1;
    float acc[8];
    #pragma unroll
    for (int c = 0; c < 8; c++) acc[c] = bias[co0+c];

    for (int ci = 0; ci < 64; ci++) {
        const float* xp = x + ((size_t)(b*64 + ci))*(HIN*HIN);
        float xv[9];
        #pragma unroll
        for (int kh = 0; kh < 3; kh++) {
            int ih = ih0 + kh;
            #pragma unroll
            for (int kw = 0; kw < 3; kw++) {
                int iw = iw0 + kw;
                bool ok = ((unsigned)ih < HIN) && ((unsigned)iw < HIN);
                xv[kh*3+kw] = ok ? xp[ih*HIN + iw] : 0.f;
            }
        }
        #pragma unroll
        for (int q = 0; q < 9; q++) {
            #pragma unroll
            for (int c = 0; c < 8; c++) acc[c] += xv[q]*ws[c][ci*9+q];
        }
    }
    float4* fp = (float4*)&g_feat[(size_t)p*64 + co0];
    fp[0] = make_float4(acc[0], acc[1], acc[2], acc[3]);
    fp[1] = make_float4(acc[4], acc[5], acc[6], acc[7]);
}

// ---------------- stage 2: fused Wh1/Wh2 GEMM + row norms/scores ----------------
__global__ void stats_linear_kernel(const float* __restrict__ W1, const float* __restrict__ W2) {
    __shared__ float sf[16][64];
    int r0 = blockIdx.x*16;
    for (int it = 0; it < 4; it++) {
        int idx = it*256 + threadIdx.x;
        sf[idx >> 6][idx & 63] = g_feat[(size_t)(r0 + (idx >> 6))*64 + (idx & 63)];
    }
    __syncthreads();
    {
        int f = threadIdx.x & 63, rs = threadIdx.x >> 6;
        float a1[4] = {0,0,0,0}, a2[4] = {0,0,0,0};
        #pragma unroll 8
        for (int k = 0; k < 64; k++) {
            float w1 = W1[k*64+f], w2 = W2[k*64+f];
            #pragma unroll
            for (int r = 0; r < 4; r++) {
                float hv = sf[rs*4+r][k];
                a1[r] += hv*w1; a2[r] += hv*w2;
            }
        }
        #pragma unroll
        for (int r = 0; r < 4; r++) {
            int row = r0 + rs*4 + r;
            g_Wh1[(size_t)row*64+f] = a1[r];
            g_Wh2[(size_t)row*64+f] = a2[r];
        }
    }
    // stats: 16 rows x 16 lanes, 4 k each
    {
        int lr = threadIdx.x >> 4, ln = threadIdx.x & 15;
        float p0=0.f,p1=0.f,p2=0.f,p3=0.f,p4=0.f;
        #pragma unroll
        for (int q = 0; q < 4; q++) {
            int k = ln*4 + q;
            float hv = sf[lr][k];
            p0 += hv*hv;
            p1 += hv*g_v[k];      p2 += hv*g_v[64+k];
            p3 += hv*g_v[128+k];  p4 += hv*g_v[192+k];
        }
        #pragma unroll
        for (int off = 8; off; off >>= 1) {
            p0 += __shfl_xor_sync(0xffffffffu, p0, off);
            p1 += __shfl_xor_sync(0xffffffffu, p1, off);
            p2 += __shfl_xor_sync(0xffffffffu, p2, off);
            p3 += __shfl_xor_sync(0xffffffffu, p3, off);
            p4 += __shfl_xor_sync(0xffffffffu, p4, off);
        }
        if (ln == 0) {
            int row = r0 + lr;
            g_sq[row]  = p0;
            g_s11[row] = p1; g_s21[row] = p2;
            g_s12[row] = p3; g_s22[row] = p4;
        }
    }
}

// ---------------- fused dist + top-7 (per j-split) ----------------
__device__ __forceinline__ void ins7(unsigned long long* L, unsigned long long key) {
    if (key < L[6]) {
        L[6] = key;
        #pragma unroll
        for (int q = 6; q > 0; q--) {
            unsigned long long a = L[q-1], b = L[q];
            L[q-1] = a < b ? a : b;
            L[q]   = a < b ? b : a;
        }
    }
}

__global__ void knn_kernel() {
    __shared__ float As[64][65];
    __shared__ __align__(16) float BD[64][65];   // Bs during GEMM, then d2 tile, then cand
    unsigned long long* cand = (unsigned long long*)&BD[0][0];

    int s = blockIdx.x, itile = blockIdx.y, b = blockIdx.z;
    int i0 = itile*64;
    int t = threadIdx.x;
    for (int q = 0; q < 16; q++) {
        int idx = q*256 + t; int r = idx>>6, c = idx&63;
        As[r][c] = g_feat[(size_t)(b*NN + i0 + r)*64 + c];
    }
    int tx = t&15, ty = t>>4;
    float sqi[4];
    #pragma unroll
    for (int m = 0; m < 4; m++) sqi[m] = g_sq[b*NN + i0 + ty + 16*m];
    int srow = t>>2, sch = t&3;
    unsigned long long list[7];
    #pragma unroll
    for (int k = 0; k < 7; k++) list[k] = ~0ull;

    for (int jt = 0; jt < JT_PER; jt++) {
        int j0 = (s*JT_PER + jt)*64;
        __syncthreads();                       // prev selection reads done
        for (int q = 0; q < 16; q++) {
            int idx = q*256 + t; int r = idx>>6, c = idx&63;
            BD[r][c] = g_feat[(size_t)(b*NN + j0 + r)*64 + c];
        }
        __syncthreads();
        float acc[4][4];
        #pragma unroll
        for (int mi = 0; mi < 4; mi++)
            #pragma unroll
            for (int mj = 0; mj < 4; mj++) acc[mi][mj] = 0.f;
        #pragma unroll 8
        for (int c = 0; c < 64; c++) {
            float av[4], bv[4];
            #pragma unroll
            for (int m = 0; m < 4; m++) { av[m] = As[ty+16*m][c]; bv[m] = BD[tx+16*m][c]; }
            #pragma unroll
            for (int mi = 0; mi < 4; mi++)
                #pragma unroll
                for (int mj = 0; mj < 4; mj++) acc[mi][mj] += av[mi]*bv[mj];
        }
        float sqj[4];
        #pragma unroll
        for (int m = 0; m < 4; m++) sqj[m] = g_sq[b*NN + j0 + tx + 16*m];
        __syncthreads();                       // all Bs reads done; reuse as d2
        #pragma unroll
        for (int mi = 0; mi < 4; mi++)
            #pragma unroll
            for (int mj = 0; mj < 4; mj++)
                BD[ty+16*mi][tx+16*mj] = fmaxf(sqi[mi] + sqj[mj] - 2.f*acc[mi][mj], 0.f);
        __syncthreads();
        #pragma unroll
        for (int q = 0; q < 16; q++) {
            int jl = sch*16 + q;
            unsigned long long key =
                ((unsigned long long)__float_as_uint(BD[srow][jl]) << 32) | (unsigned)(j0 + jl);
            ins7(list, key);
        }
    }
    __syncthreads();
    #pragma unroll
    for (int k = 0; k < 7; k++) cand[srow*28 + sch*7 + k] = list[k];
    __syncthreads();
    if (t < 64) {
        int ptr[4] = {0,0,0,0};
        unsigned long long* c4 = &cand[t*28];
        unsigned long long* go = &g_cand[((size_t)(b*NN + i0 + t)*JSPLIT + s)*KK];
        for (int k = 0; k < KK; k++) {
            int bq = 0; unsigned long long bk = ~0ull;
            #pragma unroll
            for (int q = 0; q < 4; q++) {
                if (ptr[q] < 7) {
                    unsigned long long v = c4[q*7 + ptr[q]];
                    if (v < bk) { bk = v; bq = q; }
                }
            }
            ptr[bq]++;
            go[k] = bk;
        }
    }
}

__global__ void knn_merge_kernel() {
    int row = blockIdx.x*256 + threadIdx.x;
    if (row >= NROWS) return;
    const unsigned long long* c = &g_cand[(size_t)row*JSPLIT*KK];
    int ptr[JSPLIT];
    #pragma unroll
    for (int q = 0; q < JSPLIT; q++) ptr[q] = 0;
    int bbase = (row / NN) * NN;
    for (int k = 0; k < KK; k++) {
        int bq = 0; unsigned long long bk = ~0ull;
        #pragma unroll
        for (int q = 0; q < JSPLIT; q++) {
            if (ptr[q] < KK) {
                unsigned long long v = c[q*KK + ptr[q]];
                if (v < bk) { bk = v; bq = q; }
            }
        }
        ptr[bq]++;
        g_nbr[row*KK + k] = bbase + (int)(bk & 0xffffffffu);
    }
}

// ---------------- fused: head aggregation + output linear + output scores ----------------
// 16 rows per block, 256 threads; hcat lives only in smem.
__global__ void gat_fused_kernel(const float* __restrict__ Wout) {
    __shared__ float sf[16][128];
    __shared__ int   jn[16][KK];
    __shared__ float e1[16][KK], e2[16][KK];
    int r0 = blockIdx.x*16;
    int g = threadIdx.x >> 6, f = threadIdx.x & 63;

    #pragma unroll
    for (int rr = 0; rr < 4; rr++) {
        int lr = rr*4 + g;
        int row = r0 + lr;
        if (f < KK) {
            int j = g_nbr[row*KK + f];
            jn[lr][f] = j;
            float v1 = g_s11[row] + g_s21[j];
            float v2 = g_s12[row] + g_s22[j];
            e1[lr][f] = v1 > 0.f ? v1 : 0.2f*v1;
            e2[lr][f] = v2 > 0.f ? v2 : 0.2f*v2;
        }
    }
    __syncthreads();
    #pragma unroll
    for (int rr = 0; rr < 4; rr++) {
        int lr = rr*4 + g;
        float m1 = -INFINITY, m2 = -INFINITY;
        #pragma unroll
        for (int k = 0; k < KK; k++) { m1 = fmaxf(m1, e1[lr][k]); m2 = fmaxf(m2, e2[lr][k]); }
        float w1[KK], w2[KK], s1 = 0.f, s2 = 0.f;
        #pragma unroll
        for (int k = 0; k < KK; k++) {
            w1[k] = expf(e1[lr][k]-m1); s1 += w1[k];
            w2[k] = expf(e2[lr][k]-m2); s2 += w2[k];
        }
        float i1 = 1.f/s1, i2 = 1.f/s2;
        float acc1 = 0.f, acc2 = 0.f;
        #pragma unroll
        for (int k = 0; k < KK; k++) {
            int j = jn[lr][k];
            acc1 += (w1[k]*i1)*g_Wh1[(size_t)j*64+f];
            acc2 += (w2[k]*i2)*g_Wh2[(size_t)j*64+f];
        }
        acc1 = acc1 > 0.f ? acc1 : (expf(acc1)-1.f);
        acc2 = acc2 > 0.f ? acc2 : (expf(acc2)-1.f);
        sf[lr][f]      = acc1;
        sf[lr][64 + f] = acc2;
    }
    __syncthreads();
    // output linear: Who = hcat @ Wout
    {
        int rs = threadIdx.x >> 6;
        float acc[4] = {0,0,0,0};
        #pragma unroll 8
        for (int k = 0; k < 128; k++) {
            float wv = Wout[k*64+f];
            #pragma unroll
            for (int r = 0; r < 4; r++) acc[r] += sf[rs*4+r][k]*wv;
        }
        #pragma unroll
        for (int r = 0; r < 4; r++)
            g_Who[(size_t)(r0 + rs*4 + r)*64+f] = acc[r];
    }
    // output scores: so1/so2 from hcat; 16 rows x 16 lanes, 8 k each
    {
        int lr = threadIdx.x >> 4, ln = threadIdx.x & 15;
        float p1 = 0.f, p2 = 0.f;
        #pragma unroll
        for (int q = 0; q < 8; q++) {
            int k = ln*8 + q;
            float hv = sf[lr][k];
            p1 += hv*g_v[256+k]; p2 += hv*g_v[384+k];
        }
        #pragma unroll
        for (int off = 8; off; off >>= 1) {
            p1 += __shfl_xor_sync(0xffffffffu, p1, off);
            p2 += __shfl_xor_sync(0xffffffffu, p2, off);
        }
        if (ln == 0) {
            g_so1[r0 + lr] = p1;
            g_so2[r0 + lr] = p2;
        }
    }
}

// ---------------- output aggregation -> g_gT ----------------
__global__ void gat_out_kernel() {
    int g = threadIdx.x >> 6, f = threadIdx.x & 63;
    int row = blockIdx.x*4 + g;
    __shared__ int   jn[4][KK];
    __shared__ float ee[4][KK];
    if (f < KK) {
        int j = g_nbr[row*KK + f];
        jn[g][f] = j;
        float v = g_so1[row] + g_so2[j];
        ee[g][f] = v > 0.f ? v : 0.2f*v;
    }
    __syncthreads();
    float mx = -INFINITY;
    #pragma unroll
    for (int k = 0; k < KK; k++) mx = fmaxf(mx, ee[g][k]);
    float wk[KK], sum = 0.f;
    #pragma unroll
    for (int k = 0; k < KK; k++) { wk[k] = expf(ee[g][k]-mx); sum += wk[k]; }
    float inv = 1.f/sum, acc = 0.f;
    #pragma unroll
    for (int k = 0; k < KK; k++) acc += (wk[k]*inv)*g_Who[(size_t)jn[g][k]*64+f];
    acc = acc > 0.f ? acc : (expf(acc)-1.f);
    int b = row / NN, n = row % NN;
    g_gT[(size_t)(b*64 + f)*NN + n] = acc;
}

// ---------------- transpose conv: parity-class blocking + 8-co tiling ----------------
__global__ void tconv_kernel(const float* __restrict__ tw, const float* __restrict__ bias,
                             float* __restrict__ out) {
    __shared__ float ws[8*576];   // [co_l][ci*9 + q]
    int co0 = blockIdx.y*8;
    for (int idx = threadIdx.x; idx < 8*576; idx += 256) {
        int co_l = idx/576, rem = idx%576, ci = rem/9, q = rem%9;
        ws[idx] = tw[((size_t)(ci*64 + co0 + co_l))*9 + q];
    }
    __syncthreads();

    int cls = blockIdx.z;
    int px = cls & 1, py = cls >> 1;
    int p2 = blockIdx.x*256 + threadIdx.x;      // [0, 4608)
    int xw = p2 % HH;
    int yh = (p2 / HH) % HH;
    int b  = p2 / (HH*HH);
    int ow = 2*xw + px, oh = 2*yh + py;

    float acc[8];
    #pragma unroll
    for (int c = 0; c < 8; c++) acc[c] = bias[co0+c];

    const float* gbase = g_gT + (size_t)b*64*NN;
    #pragma unroll
    for (int kh = 0; kh < 3; kh++) {
        int t_ = oh + 1 - kh;
        if (t_ & 1) continue;                   // warp-uniform
        int ih = t_ >> 1; if ((unsigned)ih >= HH) continue;
        #pragma unroll
        for (int kw = 0; kw < 3; kw++) {
            int u = ow + 1 - kw;
            if (u & 1) continue;                // warp-uniform
            int iw = u >> 1; if ((unsigned)iw >= HH) continue;
            const float* gp = gbase + ih*HH + iw;
            int qq = kh*3 + kw;
            #pragma unroll 8
            for (int ci = 0; ci < 64; ci++) {
                float gv = gp[(size_t)ci*NN];
                #pragma unroll
                for (int c = 0; c < 8; c++) acc[c] += gv * ws[c*576 + ci*9 + qq];
            }
        }
    }
    #pragma unroll
    for (int c = 0; c < 8; c++)
        out[((size_t)(b*64 + co0 + c))*(HIN*HIN) + oh*HIN + ow] = acc[c];
}

// ---------------- launcher ----------------
extern "C" void kernel_launch(void* const* d_in, const int* in_sizes, int n_in,
                              void* d_out, int out_size) {
    const float* x       = (const float*)d_in[0];
    const float* conv_w  = (const float*)d_in[1];
    const float* conv_b  = (const float*)d_in[2];
    const float* W1      = (const float*)d_in[3];
    const float* a1      = (const float*)d_in[4];
    const float* W2      = (const float*)d_in[5];
    const float* a2      = (const float*)d_in[6];
    const float* Wout    = (const float*)d_in[7];
    const float* aout    = (const float*)d_in[8];
    const float* tconv_w = (const float*)d_in[9];
    const float* tconv_b = (const float*)d_in[10];
    float* out = (float*)d_out;

    prep_vecs_kernel<<<1, 128>>>(W1, a1, W2, a2, Wout, aout);
    conv_kernel<<<dim3(36, 8), 128>>>(x, conv_w, conv_b);
    stats_linear_kernel<<<NROWS/16, 256>>>(W1, W2);
    knn_kernel<<<dim3(JSPLIT, 36, 2), 256>>>();
    knn_merge_kernel<<<NROWS/256, 256>>>();
    gat_fused_kernel<<<NROWS/16, 256>>>(Wout);
    gat_out_kernel<<<NROWS/4, 256>>>();
    tconv_kernel<<<dim3(18, 8, 4), 256>>>(tconv_w, tconv_b, out);
}

// round 6
// speedup vs baseline: 4.9239x; 1.0621x over previous
#include <cuda_runtime.h>
#include <math.h>

#define BB 2
#define CIN 64
#define CC 64
#define HIN 96
#define HH 48
#define NN 2304
#define KK 7
#define NROWS 4608
#define JSPLIT 12
#define JT_PER 3            /* 36 j-tiles / JSPLIT */

// ---------------- scratch ----------------
__device__ float g_feat[NROWS*CC];
__device__ float g_sq[NROWS];
__device__ int   g_nbr[NROWS*KK];
__device__ unsigned long long g_cand[(size_t)NROWS*JSPLIT*KK];
__device__ float g_Wh1[NROWS*CC];
__device__ float g_Wh2[NROWS*CC];
__device__ float g_Who[NROWS*CC];
__device__ float g_gT[BB*CC*NN];
__device__ float g_s11[NROWS], g_s21[NROWS], g_s12[NROWS], g_s22[NROWS];
__device__ float g_so1[NROWS], g_so2[NROWS];
__device__ float g_v[512];

// ---------------- stage 0: fold attention vectors through W ----------------
__global__ void prep_vecs_kernel(const float* __restrict__ W1, const float* __restrict__ a1,
                                 const float* __restrict__ W2, const float* __restrict__ a2,
                                 const float* __restrict__ Wout, const float* __restrict__ aout) {
    int k = threadIdx.x;  // 128
    if (k < 64) {
        float s=0.f,t=0.f,u=0.f,v=0.f;
        for (int f = 0; f < 64; f++) {
            float w1 = W1[k*64+f]; s += w1*a1[f]; t += w1*a1[64+f];
            float w2 = W2[k*64+f]; u += w2*a2[f]; v += w2*a2[64+f];
        }
        g_v[k]=s; g_v[64+k]=t; g_v[128+k]=u; g_v[192+k]=v;
    }
    {
        float s=0.f,t=0.f;
        for (int f = 0; f < 64; f++) {
            float wo = Wout[k*64+f]; s += wo*aout[f]; t += wo*aout[64+f];
        }
        g_v[256+k]=s; g_v[384+k]=t;
    }
}

// ---------------- stage 1: stride-2 conv (1 px x 8 co per thread) ----------------
__global__ void conv_kernel(const float* __restrict__ x, const float* __restrict__ w,
                            const float* __restrict__ bias) {
    __shared__ float ws[8][576];
    int co0 = blockIdx.y * 8;
    for (int idx = threadIdx.x; idx < 8*576; idx += 128)
        ws[idx/576][idx%576] = w[co0*576 + idx];
    __syncthreads();

    int p = blockIdx.x*128 + threadIdx.x;   // [0, 4608)
    int b = p / NN;
    int n = p % NN;
    int ih0 = (n / HH)*2 - 1;
    int iw0 = (n % HH)*2 - 1;

    // hoist bounds + offsets out of the ci loop
    bool ok[9]; int off[9];
    #pragma unroll
    for (int kh = 0; kh < 3; kh++)
        #pragma unroll
        for (int kw = 0; kw < 3; kw++) {
            int ih = ih0 + kh, iw = iw0 + kw;
            bool o = ((unsigned)ih < HIN) && ((unsigned)iw < HIN);
            ok[kh*3+kw] = o;
            off[kh*3+kw] = o ? (ih*HIN + iw) : 0;
        }

    float acc[8];
    #pragma unroll
    for (int c = 0; c < 8; c++) acc[c] = bias[co0+c];

    const float* xp = x + (size_t)b*64*(HIN*HIN);
    for (int ci = 0; ci < 64; ci++, xp += HIN*HIN) {
        float xv[9];
        #pragma unroll
        for (int q = 0; q < 9; q++) xv[q] = ok[q] ? xp[off[q]] : 0.f;
        #pragma unroll
        for (int q = 0; q < 9; q++) {
            #pragma unroll
            for (int c = 0; c < 8; c++) acc[c] += xv[q]*ws[c][ci*9+q];
        }
    }
    float4* fp = (float4*)&g_feat[(size_t)p*64 + co0];
    fp[0] = make_float4(acc[0], acc[1], acc[2], acc[3]);
    fp[1] = make_float4(acc[4], acc[5], acc[6], acc[7]);
}

// ---------------- stage 2: fused Wh1/Wh2 GEMM + row norms/scores ----------------
__global__ void stats_linear_kernel(const float* __restrict__ W1, const float* __restrict__ W2) {
    __shared__ float sf[16][64];
    int r0 = blockIdx.x*16;
    for (int it = 0; it < 4; it++) {
        int idx = it*256 + threadIdx.x;
        sf[idx >> 6][idx & 63] = g_feat[(size_t)(r0 + (idx >> 6))*64 + (idx & 63)];
    }
    __syncthreads();
    {
        int f = threadIdx.x & 63, rs = threadIdx.x >> 6;
        float a1[4] = {0,0,0,0}, a2[4] = {0,0,0,0};
        #pragma unroll 8
        for (int k = 0; k < 64; k++) {
            float w1 = W1[k*64+f], w2 = W2[k*64+f];
            #pragma unroll
            for (int r = 0; r < 4; r++) {
                float hv = sf[rs*4+r][k];
                a1[r] += hv*w1; a2[r] += hv*w2;
            }
        }
        #pragma unroll
        for (int r = 0; r < 4; r++) {
            int row = r0 + rs*4 + r;
            g_Wh1[(size_t)row*64+f] = a1[r];
            g_Wh2[(size_t)row*64+f] = a2[r];
        }
    }
    {
        int lr = threadIdx.x >> 4, ln = threadIdx.x & 15;
        float p0=0.f,p1=0.f,p2=0.f,p3=0.f,p4=0.f;
        #pragma unroll
        for (int q = 0; q < 4; q++) {
            int k = ln*4 + q;
            float hv = sf[lr][k];
            p0 += hv*hv;
            p1 += hv*g_v[k];      p2 += hv*g_v[64+k];
            p3 += hv*g_v[128+k];  p4 += hv*g_v[192+k];
        }
        #pragma unroll
        for (int off = 8; off; off >>= 1) {
            p0 += __shfl_xor_sync(0xffffffffu, p0, off);
            p1 += __shfl_xor_sync(0xffffffffu, p1, off);
            p2 += __shfl_xor_sync(0xffffffffu, p2, off);
            p3 += __shfl_xor_sync(0xffffffffu, p3, off);
            p4 += __shfl_xor_sync(0xffffffffu, p4, off);
        }
        if (ln == 0) {
            int row = r0 + lr;
            g_sq[row]  = p0;
            g_s11[row] = p1; g_s21[row] = p2;
            g_s12[row] = p3; g_s22[row] = p4;
        }
    }
}

// ---------------- fused dist + top-7 (per j-split), f32 keys ----------------
__global__ void knn_kernel() {
    __shared__ float As[64][66];
    __shared__ __align__(16) float BD[64][66];   // Bs during GEMM, then d2, then cand
    unsigned long long* cand = (unsigned long long*)&BD[0][0];  // 14336B < 16896B

    int s = blockIdx.x, itile = blockIdx.y, b = blockIdx.z;
    int i0 = itile*64;
    int t = threadIdx.x;
    for (int q = 0; q < 16; q++) {
        int idx = q*256 + t; int r = idx>>6, c = idx&63;
        As[r][c] = g_feat[(size_t)(b*NN + i0 + r)*64 + c];
    }
    int tx = t&15, ty = t>>4;
    float sqi[4];
    #pragma unroll
    for (int m = 0; m < 4; m++) sqi[m] = g_sq[b*NN + i0 + ty + 16*m];
    int srow = t>>2, sch = t&3;
    float lv[7]; int li[7];
    #pragma unroll
    for (int k = 0; k < 7; k++) { lv[k] = INFINITY; li[k] = 0x7fffffff; }

    for (int jt = 0; jt < JT_PER; jt++) {
        int j0 = (s*JT_PER + jt)*64;
        __syncthreads();                       // prev selection reads done
        for (int q = 0; q < 16; q++) {
            int idx = q*256 + t; int r = idx>>6, c = idx&63;
            BD[r][c] = g_feat[(size_t)(b*NN + j0 + r)*64 + c];
        }
        __syncthreads();
        float acc[4][4];
        #pragma unroll
        for (int mi = 0; mi < 4; mi++)
            #pragma unroll
            for (int mj = 0; mj < 4; mj++) acc[mi][mj] = 0.f;
        #pragma unroll 8
        for (int c2 = 0; c2 < 32; c2++) {
            float2 av[4], bv[4];
            #pragma unroll
            for (int m = 0; m < 4; m++) {
                av[m] = *(const float2*)&As[ty+16*m][2*c2];
                bv[m] = *(const float2*)&BD[tx+16*m][2*c2];
            }
            #pragma unroll
            for (int mi = 0; mi < 4; mi++)
                #pragma unroll
                for (int mj = 0; mj < 4; mj++) {
                    acc[mi][mj] += av[mi].x*bv[mj].x;
                    acc[mi][mj] += av[mi].y*bv[mj].y;
                }
        }
        float sqj[4];
        #pragma unroll
        for (int m = 0; m < 4; m++) sqj[m] = g_sq[b*NN + j0 + tx + 16*m];
        __syncthreads();                       // all Bs reads done; reuse as d2
        #pragma unroll
        for (int mi = 0; mi < 4; mi++)
            #pragma unroll
            for (int mj = 0; mj < 4; mj++)
                BD[ty+16*mi][tx+16*mj] = fmaxf(sqi[mi] + sqj[mj] - 2.f*acc[mi][mj], 0.f);
        __syncthreads();
        // selection: candidates arrive in strictly increasing j within this thread,
        // so strict-< float insertion preserves stable-argsort tie semantics.
        #pragma unroll
        for (int q = 0; q < 16; q++) {
            int jl = sch*16 + q;
            float v = BD[srow][jl];
            if (v < lv[6]) {
                lv[6] = v; li[6] = j0 + jl;
                #pragma unroll
                for (int p = 6; p > 0; p--) {
                    bool sw = lv[p] < lv[p-1];
                    float tv = lv[p-1]; int ti = li[p-1];
                    lv[p-1] = sw ? lv[p] : lv[p-1];
                    li[p-1] = sw ? li[p] : li[p-1];
                    lv[p]   = sw ? tv : lv[p];
                    li[p]   = sw ? ti : li[p];
                }
            }
        }
    }
    __syncthreads();
    #pragma unroll
    for (int k = 0; k < 7; k++)
        cand[srow*28 + sch*7 + k] =
            ((unsigned long long)__float_as_uint(lv[k]) << 32) | (unsigned)li[k];
    __syncthreads();
    if (t < 64) {
        int ptr[4] = {0,0,0,0};
        unsigned long long* c4 = &cand[t*28];
        unsigned long long* go = &g_cand[((size_t)(b*NN + i0 + t)*JSPLIT + s)*KK];
        for (int k = 0; k < KK; k++) {
            int bq = 0; unsigned long long bk = ~0ull;
            #pragma unroll
            for (int q = 0; q < 4; q++) {
                if (ptr[q] < 7) {
                    unsigned long long v = c4[q*7 + ptr[q]];
                    if (v < bk) { bk = v; bq = q; }
                }
            }
            ptr[bq]++;
            go[k] = bk;
        }
    }
}

__global__ void knn_merge_kernel() {
    int row = blockIdx.x*64 + threadIdx.x;
    if (row >= NROWS) return;
    const unsigned long long* c = &g_cand[(size_t)row*JSPLIT*KK];
    int ptr[JSPLIT];
    #pragma unroll
    for (int q = 0; q < JSPLIT; q++) ptr[q] = 0;
    int bbase = (row / NN) * NN;
    for (int k = 0; k < KK; k++) {
        int bq = 0; unsigned long long bk = ~0ull;
        #pragma unroll
        for (int q = 0; q < JSPLIT; q++) {
            if (ptr[q] < KK) {
                unsigned long long v = c[q*KK + ptr[q]];
                if (v < bk) { bk = v; bq = q; }
            }
        }
        ptr[bq]++;
        g_nbr[row*KK + k] = bbase + (int)(bk & 0xffffffffu);
    }
}

// ---------------- fused: head aggregation + output linear + output scores ----------------
__global__ void gat_fused_kernel(const float* __restrict__ Wout) {
    __shared__ float sf[16][128];
    __shared__ int   jn[16][KK];
    __shared__ float e1[16][KK], e2[16][KK];
    int r0 = blockIdx.x*16;
    int g = threadIdx.x >> 6, f = threadIdx.x & 63;

    #pragma unroll
    for (int rr = 0; rr < 4; rr++) {
        int lr = rr*4 + g;
        int row = r0 + lr;
        if (f < KK) {
            int j = g_nbr[row*KK + f];
            jn[lr][f] = j;
            float v1 = g_s11[row] + g_s21[j];
            float v2 = g_s12[row] + g_s22[j];
            e1[lr][f] = v1 > 0.f ? v1 : 0.2f*v1;
            e2[lr][f] = v2 > 0.f ? v2 : 0.2f*v2;
        }
    }
    __syncthreads();
    #pragma unroll
    for (int rr = 0; rr < 4; rr++) {
        int lr = rr*4 + g;
        float m1 = -INFINITY, m2 = -INFINITY;
        #pragma unroll
        for (int k = 0; k < KK; k++) { m1 = fmaxf(m1, e1[lr][k]); m2 = fmaxf(m2, e2[lr][k]); }
        float w1[KK], w2[KK], s1 = 0.f, s2 = 0.f;
        #pragma unroll
        for (int k = 0; k < KK; k++) {
            w1[k] = expf(e1[lr][k]-m1); s1 += w1[k];
            w2[k] = expf(e2[lr][k]-m2); s2 += w2[k];
        }
        float i1 = 1.f/s1, i2 = 1.f/s2;
        float acc1 = 0.f, acc2 = 0.f;
        #pragma unroll
        for (int k = 0; k < KK; k++) {
            int j = jn[lr][k];
            acc1 += (w1[k]*i1)*g_Wh1[(size_t)j*64+f];
            acc2 += (w2[k]*i2)*g_Wh2[(size_t)j*64+f];
        }
        acc1 = acc1 > 0.f ? acc1 : (expf(acc1)-1.f);
        acc2 = acc2 > 0.f ? acc2 : (expf(acc2)-1.f);
        sf[lr][f]      = acc1;
        sf[lr][64 + f] = acc2;
    }
    __syncthreads();
    {
        int rs = threadIdx.x >> 6;
        float acc[4] = {0,0,0,0};
        #pragma unroll 8
        for (int k = 0; k < 128; k++) {
            float wv = Wout[k*64+f];
            #pragma unroll
            for (int r = 0; r < 4; r++) acc[r] += sf[rs*4+r][k]*wv;
        }
        #pragma unroll
        for (int r = 0; r < 4; r++)
            g_Who[(size_t)(r0 + rs*4 + r)*64+f] = acc[r];
    }
    {
        int lr = threadIdx.x >> 4, ln = threadIdx.x & 15;
        float p1 = 0.f, p2 = 0.f;
        #pragma unroll
        for (int q = 0; q < 8; q++) {
            int k = ln*8 + q;
            float hv = sf[lr][k];
            p1 += hv*g_v[256+k]; p2 += hv*g_v[384+k];
        }
        #pragma unroll
        for (int off = 8; off; off >>= 1) {
            p1 += __shfl_xor_sync(0xffffffffu, p1, off);
            p2 += __shfl_xor_sync(0xffffffffu, p2, off);
        }
        if (ln == 0) {
            g_so1[r0 + lr] = p1;
            g_so2[r0 + lr] = p2;
        }
    }
}

// ---------------- output aggregation -> g_gT ----------------
__global__ void gat_out_kernel() {
    int g = threadIdx.x >> 6, f = threadIdx.x & 63;
    int row = blockIdx.x*4 + g;
    __shared__ int   jn[4][KK];
    __shared__ float ee[4][KK];
    if (f < KK) {
        int j = g_nbr[row*KK + f];
        jn[g][f] = j;
        float v = g_so1[row] + g_so2[j];
        ee[g][f] = v > 0.f ? v : 0.2f*v;
    }
    __syncthreads();
    float mx = -INFINITY;
    #pragma unroll
    for (int k = 0; k < KK; k++) mx = fmaxf(mx, ee[g][k]);
    float wk[KK], sum = 0.f;
    #pragma unroll
    for (int k = 0; k < KK; k++) { wk[k] = expf(ee[g][k]-mx); sum += wk[k]; }
    float inv = 1.f/sum, acc = 0.f;
    #pragma unroll
    for (int k = 0; k < KK; k++) acc += (wk[k]*inv)*g_Who[(size_t)jn[g][k]*64+f];
    acc = acc > 0.f ? acc : (expf(acc)-1.f);
    int b = row / NN, n = row % NN;
    g_gT[(size_t)(b*64 + f)*NN + n] = acc;
}

// ---------------- transpose conv: parity-class blocking + 8-co tiling ----------------
__global__ void tconv_kernel(const float* __restrict__ tw, const float* __restrict__ bias,
                             float* __restrict__ out) {
    __shared__ float ws[8*576];
    int co0 = blockIdx.y*8;
    for (int idx = threadIdx.x; idx < 8*576; idx += 256) {
        int co_l = idx/576, rem = idx%576, ci = rem/9, q = rem%9;
        ws[idx] = tw[((size_t)(ci*64 + co0 + co_l))*9 + q];
    }
    __syncthreads();

    int cls = blockIdx.z;
    int px = cls & 1, py = cls >> 1;
    int p2 = blockIdx.x*256 + threadIdx.x;
    int xw = p2 % HH;
    int yh = (p2 / HH) % HH;
    int b  = p2 / (HH*HH);
    int ow = 2*xw + px, oh = 2*yh + py;

    float acc[8];
    #pragma unroll
    for (int c = 0; c < 8; c++) acc[c] = bias[co0+c];

    const float* gbase = g_gT + (size_t)b*64*NN;
    #pragma unroll
    for (int kh = 0; kh < 3; kh++) {
        int t_ = oh + 1 - kh;
        if (t_ & 1) continue;
        int ih = t_ >> 1; if ((unsigned)ih >= HH) continue;
        #pragma unroll
        for (int kw = 0; kw < 3; kw++) {
            int u = ow + 1 - kw;
            if (u & 1) continue;
            int iw = u >> 1; if ((unsigned)iw >= HH) continue;
            const float* gp = gbase + ih*HH + iw;
            int qq = kh*3 + kw;
            #pragma unroll 8
            for (int ci = 0; ci < 64; ci++) {
                float gv = gp[(size_t)ci*NN];
                #pragma unroll
                for (int c = 0; c < 8; c++) acc[c] += gv * ws[c*576 + ci*9 + qq];
            }
        }
    }
    #pragma unroll
    for (int c = 0; c < 8; c++)
        out[((size_t)(b*64 + co0 + c))*(HIN*HIN) + oh*HIN + ow] = acc[c];
}

// ---------------- launcher ----------------
extern "C" void kernel_launch(void* const* d_in, const int* in_sizes, int n_in,
                              void* d_out, int out_size) {
    const float* x       = (const float*)d_in[0];
    const float* conv_w  = (const float*)d_in[1];
    const float* conv_b  = (const float*)d_in[2];
    const float* W1      = (const float*)d_in[3];
    const float* a1      = (const float*)d_in[4];
    const float* W2      = (const float*)d_in[5];
    const float* a2      = (const float*)d_in[6];
    const float* Wout    = (const float*)d_in[7];
    const float* aout    = (const float*)d_in[8];
    const float* tconv_w = (const float*)d_in[9];
    const float* tconv_b = (const float*)d_in[10];
    float* out = (float*)d_out;

    prep_vecs_kernel<<<1, 128>>>(W1, a1, W2, a2, Wout, aout);
    conv_kernel<<<dim3(36, 8), 128>>>(x, conv_w, conv_b);
    stats_linear_kernel<<<NROWS/16, 256>>>(W1, W2);
    knn_kernel<<<dim3(JSPLIT, 36, 2), 256>>>();
    knn_merge_kernel<<<NROWS/64, 64>>>();
    gat_fused_kernel<<<NROWS/16, 256>>>(Wout);
    gat_out_kernel<<<NROWS/4, 256>>>();
    tconv_kernel<<<dim3(18, 8, 4), 256>>>(tconv_w, tconv_b, out);
}

// round 7
// speedup vs baseline: 4.9263x; 1.0005x over previous
#include <cuda_runtime.h>
#include <math.h>

#define BB 2
#define CIN 64
#define CC 64
#define HIN 96
#define HH 48
#define NN 2304
#define KK 7
#define NROWS 4608
#define JSPLIT 12
#define JT_PER 3            /* 36 j-tiles / JSPLIT */

// ---------------- scratch ----------------
__device__ float g_feat[NROWS*CC];
__device__ float g_sq[NROWS];
__device__ int   g_nbr[NROWS*KK];
__device__ unsigned long long g_cand[(size_t)NROWS*JSPLIT*KK];
__device__ float g_Wh1[NROWS*CC];
__device__ float g_Wh2[NROWS*CC];
__device__ float g_Who[NROWS*CC];
__device__ float g_gT[BB*CC*NN];
__device__ float g_s11[NROWS], g_s21[NROWS], g_s12[NROWS], g_s22[NROWS];
__device__ float g_so1[NROWS], g_so2[NROWS];
__device__ float g_v[512];

// packed dual-lane FMA (Blackwell f32x2) — d += a*b elementwise on 2 floats
__device__ __forceinline__ void ffma2(unsigned long long& d,
                                      unsigned long long a, unsigned long long b) {
    asm("fma.rn.f32x2 %0, %1, %2, %0;" : "+l"(d) : "l"(a), "l"(b));
}

// ---------------- stage 0: fold attention vectors through W ----------------
__global__ void prep_vecs_kernel(const float* __restrict__ W1, const float* __restrict__ a1,
                                 const float* __restrict__ W2, const float* __restrict__ a2,
                                 const float* __restrict__ Wout, const float* __restrict__ aout) {
    int k = threadIdx.x;  // 128
    if (k < 64) {
        float s=0.f,t=0.f,u=0.f,v=0.f;
        for (int f = 0; f < 64; f++) {
            float w1 = W1[k*64+f]; s += w1*a1[f]; t += w1*a1[64+f];
            float w2 = W2[k*64+f]; u += w2*a2[f]; v += w2*a2[64+f];
        }
        g_v[k]=s; g_v[64+k]=t; g_v[128+k]=u; g_v[192+k]=v;
    }
    {
        float s=0.f,t=0.f;
        for (int f = 0; f < 64; f++) {
            float wo = Wout[k*64+f]; s += wo*aout[f]; t += wo*aout[64+f];
        }
        g_v[256+k]=s; g_v[384+k]=t;
    }
}

// ---------------- stage 1: stride-2 conv (1 px x 8 co per thread) ----------------
__global__ void conv_kernel(const float* __restrict__ x, const float* __restrict__ w,
                            const float* __restrict__ bias) {
    __shared__ float ws[8][576];
    int co0 = blockIdx.y * 8;
    for (int idx = threadIdx.x; idx < 8*576; idx += 128)
        ws[idx/576][idx%576] = w[co0*576 + idx];
    __syncthreads();

    int p = blockIdx.x*128 + threadIdx.x;   // [0, 4608)
    int b = p / NN;
    int n = p % NN;
    int ih0 = (n / HH)*2 - 1;
    int iw0 = (n % HH)*2 - 1;

    bool ok[9]; int off[9];
    #pragma unroll
    for (int kh = 0; kh < 3; kh++)
        #pragma unroll
        for (int kw = 0; kw < 3; kw++) {
            int ih = ih0 + kh, iw = iw0 + kw;
            bool o = ((unsigned)ih < HIN) && ((unsigned)iw < HIN);
            ok[kh*3+kw] = o;
            off[kh*3+kw] = o ? (ih*HIN + iw) : 0;
        }

    float acc[8];
    #pragma unroll
    for (int c = 0; c < 8; c++) acc[c] = bias[co0+c];

    const float* xp = x + (size_t)b*64*(HIN*HIN);
    for (int ci = 0; ci < 64; ci++, xp += HIN*HIN) {
        float xv[9];
        #pragma unroll
        for (int q = 0; q < 9; q++) xv[q] = ok[q] ? xp[off[q]] : 0.f;
        #pragma unroll
        for (int q = 0; q < 9; q++) {
            #pragma unroll
            for (int c = 0; c < 8; c++) acc[c] += xv[q]*ws[c][ci*9+q];
        }
    }
    float4* fp = (float4*)&g_feat[(size_t)p*64 + co0];
    fp[0] = make_float4(acc[0], acc[1], acc[2], acc[3]);
    fp[1] = make_float4(acc[4], acc[5], acc[6], acc[7]);
}

// ---------------- stage 2: fused Wh1/Wh2 GEMM + row norms/scores ----------------
__global__ void stats_linear_kernel(const float* __restrict__ W1, const float* __restrict__ W2) {
    __shared__ float sf[16][64];
    int r0 = blockIdx.x*16;
    for (int it = 0; it < 4; it++) {
        int idx = it*256 + threadIdx.x;
        sf[idx >> 6][idx & 63] = g_feat[(size_t)(r0 + (idx >> 6))*64 + (idx & 63)];
    }
    __syncthreads();
    {
        int f = threadIdx.x & 63, rs = threadIdx.x >> 6;
        float a1[4] = {0,0,0,0}, a2[4] = {0,0,0,0};
        #pragma unroll 8
        for (int k = 0; k < 64; k++) {
            float w1 = W1[k*64+f], w2 = W2[k*64+f];
            #pragma unroll
            for (int r = 0; r < 4; r++) {
                float hv = sf[rs*4+r][k];
                a1[r] += hv*w1; a2[r] += hv*w2;
            }
        }
        #pragma unroll
        for (int r = 0; r < 4; r++) {
            int row = r0 + rs*4 + r;
            g_Wh1[(size_t)row*64+f] = a1[r];
            g_Wh2[(size_t)row*64+f] = a2[r];
        }
    }
    {
        int lr = threadIdx.x >> 4, ln = threadIdx.x & 15;
        float p0=0.f,p1=0.f,p2=0.f,p3=0.f,p4=0.f;
        #pragma unroll
        for (int q = 0; q < 4; q++) {
            int k = ln*4 + q;
            float hv = sf[lr][k];
            p0 += hv*hv;
            p1 += hv*g_v[k];      p2 += hv*g_v[64+k];
            p3 += hv*g_v[128+k];  p4 += hv*g_v[192+k];
        }
        #pragma unroll
        for (int off = 8; off; off >>= 1) {
            p0 += __shfl_xor_sync(0xffffffffu, p0, off);
            p1 += __shfl_xor_sync(0xffffffffu, p1, off);
            p2 += __shfl_xor_sync(0xffffffffu, p2, off);
            p3 += __shfl_xor_sync(0xffffffffu, p3, off);
            p4 += __shfl_xor_sync(0xffffffffu, p4, off);
        }
        if (ln == 0) {
            int row = r0 + lr;
            g_sq[row]  = p0;
            g_s11[row] = p1; g_s21[row] = p2;
            g_s12[row] = p3; g_s22[row] = p4;
        }
    }
}

// ---------------- fused dist + top-7 (per j-split), FFMA2 GEMM ----------------
__global__ void knn_kernel() {
    __shared__ __align__(16) float As[64][66];
    __shared__ __align__(16) float BD[64][66];   // Bs during GEMM, then d2, then cand
    unsigned long long* cand = (unsigned long long*)&BD[0][0];  // 14336B < 16896B

    int s = blockIdx.x, itile = blockIdx.y, b = blockIdx.z;
    int i0 = itile*64;
    int t = threadIdx.x;
    for (int q = 0; q < 16; q++) {
        int idx = q*256 + t; int r = idx>>6, c = idx&63;
        As[r][c] = g_feat[(size_t)(b*NN + i0 + r)*64 + c];
    }
    int tx = t&15, ty = t>>4;
    float sqi[4];
    #pragma unroll
    for (int m = 0; m < 4; m++) sqi[m] = g_sq[b*NN + i0 + ty + 16*m];
    int srow = t>>2, sch = t&3;
    float lv[7]; int li[7];
    #pragma unroll
    for (int k = 0; k < 7; k++) { lv[k] = INFINITY; li[k] = 0x7fffffff; }

    for (int jt = 0; jt < JT_PER; jt++) {
        int j0 = (s*JT_PER + jt)*64;
        __syncthreads();                       // prev selection reads done
        for (int q = 0; q < 16; q++) {
            int idx = q*256 + t; int r = idx>>6, c = idx&63;
            BD[r][c] = g_feat[(size_t)(b*NN + j0 + r)*64 + c];
        }
        __syncthreads();
        unsigned long long acc2[4][4];
        #pragma unroll
        for (int mi = 0; mi < 4; mi++)
            #pragma unroll
            for (int mj = 0; mj < 4; mj++) acc2[mi][mj] = 0ull;
        #pragma unroll 8
        for (int c2 = 0; c2 < 32; c2++) {
            unsigned long long av[4], bv[4];
            #pragma unroll
            for (int m = 0; m < 4; m++) {
                av[m] = *(const unsigned long long*)&As[ty+16*m][2*c2];
                bv[m] = *(const unsigned long long*)&BD[tx+16*m][2*c2];
            }
            #pragma unroll
            for (int mi = 0; mi < 4; mi++)
                #pragma unroll
                for (int mj = 0; mj < 4; mj++)
                    ffma2(acc2[mi][mj], av[mi], bv[mj]);
        }
        float sqj[4];
        #pragma unroll
        for (int m = 0; m < 4; m++) sqj[m] = g_sq[b*NN + j0 + tx + 16*m];
        __syncthreads();                       // all Bs reads done; reuse as d2
        #pragma unroll
        for (int mi = 0; mi < 4; mi++)
            #pragma unroll
            for (int mj = 0; mj < 4; mj++) {
                float2 d = *(float2*)&acc2[mi][mj];
                float dot = d.x + d.y;
                BD[ty+16*mi][tx+16*mj] = fmaxf(sqi[mi] + sqj[mj] - 2.f*dot, 0.f);
            }
        __syncthreads();
        // per-thread candidates arrive in strictly increasing j: strict-< float
        // insertion preserves stable-argsort tie semantics.
        #pragma unroll
        for (int q = 0; q < 16; q++) {
            int jl = sch*16 + q;
            float v = BD[srow][jl];
            if (v < lv[6]) {
                lv[6] = v; li[6] = j0 + jl;
                #pragma unroll
                for (int p = 6; p > 0; p--) {
                    bool sw = lv[p] < lv[p-1];
                    float tv = lv[p-1]; int ti = li[p-1];
                    lv[p-1] = sw ? lv[p] : lv[p-1];
                    li[p-1] = sw ? li[p] : li[p-1];
                    lv[p]   = sw ? tv : lv[p];
                    li[p]   = sw ? ti : li[p];
                }
            }
        }
    }
    __syncthreads();
    #pragma unroll
    for (int k = 0; k < 7; k++)
        cand[srow*28 + sch*7 + k] =
            ((unsigned long long)__float_as_uint(lv[k]) << 32) | (unsigned)li[k];
    __syncthreads();
    if (t < 64) {
        int ptr[4] = {0,0,0,0};
        unsigned long long* c4 = &cand[t*28];
        unsigned long long* go = &g_cand[((size_t)(b*NN + i0 + t)*JSPLIT + s)*KK];
        for (int k = 0; k < KK; k++) {
            int bq = 0; unsigned long long bk = ~0ull;
            #pragma unroll
            for (int q = 0; q < 4; q++) {
                if (ptr[q] < 7) {
                    unsigned long long v = c4[q*7 + ptr[q]];
                    if (v < bk) { bk = v; bq = q; }
                }
            }
            ptr[bq]++;
            go[k] = bk;
        }
    }
}

__global__ void knn_merge_kernel() {
    int row = blockIdx.x*64 + threadIdx.x;
    if (row >= NROWS) return;
    const unsigned long long* c = &g_cand[(size_t)row*JSPLIT*KK];
    int ptr[JSPLIT];
    #pragma unroll
    for (int q = 0; q < JSPLIT; q++) ptr[q] = 0;
    int bbase = (row / NN) * NN;
    for (int k = 0; k < KK; k++) {
        int bq = 0; unsigned long long bk = ~0ull;
        #pragma unroll
        for (int q = 0; q < JSPLIT; q++) {
            if (ptr[q] < KK) {
                unsigned long long v = c[q*KK + ptr[q]];
                if (v < bk) { bk = v; bq = q; }
            }
        }
        ptr[bq]++;
        g_nbr[row*KK + k] = bbase + (int)(bk & 0xffffffffu);
    }
}

// ---------------- fused: head aggregation + output linear + output scores ----------------
__global__ void gat_fused_kernel(const float* __restrict__ Wout) {
    __shared__ float sf[16][128];
    __shared__ int   jn[16][KK];
    __shared__ float e1[16][KK], e2[16][KK];
    int r0 = blockIdx.x*16;
    int g = threadIdx.x >> 6, f = threadIdx.x & 63;

    #pragma unroll
    for (int rr = 0; rr < 4; rr++) {
        int lr = rr*4 + g;
        int row = r0 + lr;
        if (f < KK) {
            int j = g_nbr[row*KK + f];
            jn[lr][f] = j;
            float v1 = g_s11[row] + g_s21[j];
            float v2 = g_s12[row] + g_s22[j];
            e1[lr][f] = v1 > 0.f ? v1 : 0.2f*v1;
            e2[lr][f] = v2 > 0.f ? v2 : 0.2f*v2;
        }
    }
    __syncthreads();
    #pragma unroll
    for (int rr = 0; rr < 4; rr++) {
        int lr = rr*4 + g;
        float m1 = -INFINITY, m2 = -INFINITY;
        #pragma unroll
        for (int k = 0; k < KK; k++) { m1 = fmaxf(m1, e1[lr][k]); m2 = fmaxf(m2, e2[lr][k]); }
        float w1[KK], w2[KK], s1 = 0.f, s2 = 0.f;
        #pragma unroll
        for (int k = 0; k < KK; k++) {
            w1[k] = expf(e1[lr][k]-m1); s1 += w1[k];
            w2[k] = expf(e2[lr][k]-m2); s2 += w2[k];
        }
        float i1 = 1.f/s1, i2 = 1.f/s2;
        float acc1 = 0.f, acc2 = 0.f;
        #pragma unroll
        for (int k = 0; k < KK; k++) {
            int j = jn[lr][k];
            acc1 += (w1[k]*i1)*g_Wh1[(size_t)j*64+f];
            acc2 += (w2[k]*i2)*g_Wh2[(size_t)j*64+f];
        }
        acc1 = acc1 > 0.f ? acc1 : (expf(acc1)-1.f);
        acc2 = acc2 > 0.f ? acc2 : (expf(acc2)-1.f);
        sf[lr][f]      = acc1;
        sf[lr][64 + f] = acc2;
    }
    __syncthreads();
    {
        int rs = threadIdx.x >> 6;
        float acc[4] = {0,0,0,0};
        #pragma unroll 8
        for (int k = 0; k < 128; k++) {
            float wv = Wout[k*64+f];
            #pragma unroll
            for (int r = 0; r < 4; r++) acc[r] += sf[rs*4+r][k]*wv;
        }
        #pragma unroll
        for (int r = 0; r < 4; r++)
            g_Who[(size_t)(r0 + rs*4 + r)*64+f] = acc[r];
    }
    {
        int lr = threadIdx.x >> 4, ln = threadIdx.x & 15;
        float p1 = 0.f, p2 = 0.f;
        #pragma unroll
        for (int q = 0; q < 8; q++) {
            int k = ln*8 + q;
            float hv = sf[lr][k];
            p1 += hv*g_v[256+k]; p2 += hv*g_v[384+k];
        }
        #pragma unroll
        for (int off = 8; off; off >>= 1) {
            p1 += __shfl_xor_sync(0xffffffffu, p1, off);
            p2 += __shfl_xor_sync(0xffffffffu, p2, off);
        }
        if (ln == 0) {
            g_so1[r0 + lr] = p1;
            g_so2[r0 + lr] = p2;
        }
    }
}

// ---------------- output aggregation -> g_gT ----------------
__global__ void gat_out_kernel() {
    int g = threadIdx.x >> 6, f = threadIdx.x & 63;
    int row = blockIdx.x*4 + g;
    __shared__ int   jn[4][KK];
    __shared__ float ee[4][KK];
    if (f < KK) {
        int j = g_nbr[row*KK + f];
        jn[g][f] = j;
        float v = g_so1[row] + g_so2[j];
        ee[g][f] = v > 0.f ? v : 0.2f*v;
    }
    __syncthreads();
    float mx = -INFINITY;
    #pragma unroll
    for (int k = 0; k < KK; k++) mx = fmaxf(mx, ee[g][k]);
    float wk[KK], sum = 0.f;
    #pragma unroll
    for (int k = 0; k < KK; k++) { wk[k] = expf(ee[g][k]-mx); sum += wk[k]; }
    float inv = 1.f/sum, acc = 0.f;
    #pragma unroll
    for (int k = 0; k < KK; k++) acc += (wk[k]*inv)*g_Who[(size_t)jn[g][k]*64+f];
    acc = acc > 0.f ? acc : (expf(acc)-1.f);
    int b = row / NN, n = row % NN;
    g_gT[(size_t)(b*64 + f)*NN + n] = acc;
}

// ---------------- transpose conv: parity-class blocking + 8-co tiling ----------------
__global__ void tconv_kernel(const float* __restrict__ tw, const float* __restrict__ bias,
                             float* __restrict__ out) {
    __shared__ float ws[8*576];
    int co0 = blockIdx.y*8;
    for (int idx = threadIdx.x; idx < 8*576; idx += 256) {
        int co_l = idx/576, rem = idx%576, ci = rem/9, q = rem%9;
        ws[idx] = tw[((size_t)(ci*64 + co0 + co_l))*9 + q];
    }
    __syncthreads();

    int cls = blockIdx.z;
    int px = cls & 1, py = cls >> 1;
    int p2 = blockIdx.x*256 + threadIdx.x;
    int xw = p2 % HH;
    int yh = (p2 / HH) % HH;
    int b  = p2 / (HH*HH);
    int ow = 2*xw + px, oh = 2*yh + py;

    float acc[8];
    #pragma unroll
    for (int c = 0; c < 8; c++) acc[c] = bias[co0+c];

    const float* gbase = g_gT + (size_t)b*64*NN;
    #pragma unroll
    for (int kh = 0; kh < 3; kh++) {
        int t_ = oh + 1 - kh;
        if (t_ & 1) continue;
        int ih = t_ >> 1; if ((unsigned)ih >= HH) continue;
        #pragma unroll
        for (int kw = 0; kw < 3; kw++) {
            int u = ow + 1 - kw;
            if (u & 1) continue;
            int iw = u >> 1; if ((unsigned)iw >= HH) continue;
            const float* gp = gbase + ih*HH + iw;
            int qq = kh*3 + kw;
            #pragma unroll 8
            for (int ci = 0; ci < 64; ci++) {
                float gv = gp[(size_t)ci*NN];
                #pragma unroll
                for (int c = 0; c < 8; c++) acc[c] += gv * ws[c*576 + ci*9 + qq];
            }
        }
    }
    #pragma unroll
    for (int c = 0; c < 8; c++)
        out[((size_t)(b*64 + co0 + c))*(HIN*HIN) + oh*HIN + ow] = acc[c];
}

// ---------------- launcher ----------------
extern "C" void kernel_launch(void* const* d_in, const int* in_sizes, int n_in,
                              void* d_out, int out_size) {
    const float* x       = (const float*)d_in[0];
    const float* conv_w  = (const float*)d_in[1];
    const float* conv_b  = (const float*)d_in[2];
    const float* W1      = (const float*)d_in[3];
    const float* a1      = (const float*)d_in[4];
    const float* W2      = (const float*)d_in[5];
    const float* a2      = (const float*)d_in[6];
    const float* Wout    = (const float*)d_in[7];
    const float* aout    = (const float*)d_in[8];
    const float* tconv_w = (const float*)d_in[9];
    const float* tconv_b = (const float*)d_in[10];
    float* out = (float*)d_out;

    prep_vecs_kernel<<<1, 128>>>(W1, a1, W2, a2, Wout, aout);
    conv_kernel<<<dim3(36, 8), 128>>>(x, conv_w, conv_b);
    stats_linear_kernel<<<NROWS/16, 256>>>(W1, W2);
    knn_kernel<<<dim3(JSPLIT, 36, 2), 256>>>();
    knn_merge_kernel<<<NROWS/64, 64>>>();
    gat_fused_kernel<<<NROWS/16, 256>>>(Wout);
    gat_out_kernel<<<NROWS/4, 256>>>();
    tconv_kernel<<<dim3(18, 8, 4), 256>>>(tconv_w, tconv_b, out);
}

// round 8
// speedup vs baseline: 5.1213x; 1.0396x over previous
#include <cuda_runtime.h>
#include <math.h>

#define BB 2
#define CIN 64
#define CC 64
#define HIN 96
#define HH 48
#define NN 2304
#define KK 7
#define NROWS 4608
#define JSPLIT 12
#define JT_PER 3            /* 36 j-tiles / JSPLIT */

// ---------------- scratch ----------------
__device__ float g_feat[NROWS*CC];
__device__ float g_sq[NROWS];
__device__ int   g_nbr[NROWS*KK];
__device__ unsigned long long g_cand[(size_t)NROWS*JSPLIT*KK];
__device__ float g_Wh1[NROWS*CC];
__device__ float g_Wh2[NROWS*CC];
__device__ float g_Who[NROWS*CC];
__device__ float g_gT[BB*CC*NN];
__device__ float g_s11[NROWS], g_s21[NROWS], g_s12[NROWS], g_s22[NROWS];
__device__ float g_so1[NROWS], g_so2[NROWS];
__device__ float g_v[512];

// packed dual-lane FMA (Blackwell f32x2) — d += a*b elementwise on 2 floats
__device__ __forceinline__ void ffma2(unsigned long long& d,
                                      unsigned long long a, unsigned long long b) {
    asm("fma.rn.f32x2 %0, %1, %2, %0;" : "+l"(d) : "l"(a), "l"(b));
}

// ---------------- stage 0: fold attention vectors through W ----------------
__global__ void prep_vecs_kernel(const float* __restrict__ W1, const float* __restrict__ a1,
                                 const float* __restrict__ W2, const float* __restrict__ a2,
                                 const float* __restrict__ Wout, const float* __restrict__ aout) {
    int k = threadIdx.x;  // 128
    if (k < 64) {
        float s=0.f,t=0.f,u=0.f,v=0.f;
        for (int f = 0; f < 64; f++) {
            float w1 = W1[k*64+f]; s += w1*a1[f]; t += w1*a1[64+f];
            float w2 = W2[k*64+f]; u += w2*a2[f]; v += w2*a2[64+f];
        }
        g_v[k]=s; g_v[64+k]=t; g_v[128+k]=u; g_v[192+k]=v;
    }
    {
        float s=0.f,t=0.f;
        for (int f = 0; f < 64; f++) {
            float wo = Wout[k*64+f]; s += wo*aout[f]; t += wo*aout[64+f];
        }
        g_v[256+k]=s; g_v[384+k]=t;
    }
}

// ---------------- stage 1: stride-2 conv (1 px x 8 co per thread) ----------------
__global__ void conv_kernel(const float* __restrict__ x, const float* __restrict__ w,
                            const float* __restrict__ bias) {
    __shared__ float ws[8][576];
    int co0 = blockIdx.y * 8;
    for (int idx = threadIdx.x; idx < 8*576; idx += 128)
        ws[idx/576][idx%576] = w[co0*576 + idx];
    __syncthreads();

    int p = blockIdx.x*128 + threadIdx.x;   // [0, 4608)
    int b = p / NN;
    int n = p % NN;
    int ih0 = (n / HH)*2 - 1;
    int iw0 = (n % HH)*2 - 1;

    bool ok[9]; int off[9];
    #pragma unroll
    for (int kh = 0; kh < 3; kh++)
        #pragma unroll
        for (int kw = 0; kw < 3; kw++) {
            int ih = ih0 + kh, iw = iw0 + kw;
            bool o = ((unsigned)ih < HIN) && ((unsigned)iw < HIN);
            ok[kh*3+kw] = o;
            off[kh*3+kw] = o ? (ih*HIN + iw) : 0;
        }

    float acc[8];
    #pragma unroll
    for (int c = 0; c < 8; c++) acc[c] = bias[co0+c];

    const float* xp = x + (size_t)b*64*(HIN*HIN);
    for (int ci = 0; ci < 64; ci++, xp += HIN*HIN) {
        float xv[9];
        #pragma unroll
        for (int q = 0; q < 9; q++) xv[q] = ok[q] ? xp[off[q]] : 0.f;
        #pragma unroll
        for (int q = 0; q < 9; q++) {
            #pragma unroll
            for (int c = 0; c < 8; c++) acc[c] += xv[q]*ws[c][ci*9+q];
        }
    }
    float4* fp = (float4*)&g_feat[(size_t)p*64 + co0];
    fp[0] = make_float4(acc[0], acc[1], acc[2], acc[3]);
    fp[1] = make_float4(acc[4], acc[5], acc[6], acc[7]);
}

// ---------------- stage 2: fused Wh1/Wh2 GEMM + row norms/scores ----------------
__global__ void stats_linear_kernel(const float* __restrict__ W1, const float* __restrict__ W2) {
    __shared__ float sf[16][64];
    int r0 = blockIdx.x*16;
    for (int it = 0; it < 4; it++) {
        int idx = it*256 + threadIdx.x;
        sf[idx >> 6][idx & 63] = g_feat[(size_t)(r0 + (idx >> 6))*64 + (idx & 63)];
    }
    __syncthreads();
    {
        int f = threadIdx.x & 63, rs = threadIdx.x >> 6;
        float a1[4] = {0,0,0,0}, a2[4] = {0,0,0,0};
        #pragma unroll 8
        for (int k = 0; k < 64; k++) {
            float w1 = W1[k*64+f], w2 = W2[k*64+f];
            #pragma unroll
            for (int r = 0; r < 4; r++) {
                float hv = sf[rs*4+r][k];
                a1[r] += hv*w1; a2[r] += hv*w2;
            }
        }
        #pragma unroll
        for (int r = 0; r < 4; r++) {
            int row = r0 + rs*4 + r;
            g_Wh1[(size_t)row*64+f] = a1[r];
            g_Wh2[(size_t)row*64+f] = a2[r];
        }
    }
    {
        int lr = threadIdx.x >> 4, ln = threadIdx.x & 15;
        float p0=0.f,p1=0.f,p2=0.f,p3=0.f,p4=0.f;
        #pragma unroll
        for (int q = 0; q < 4; q++) {
            int k = ln*4 + q;
            float hv = sf[lr][k];
            p0 += hv*hv;
            p1 += hv*g_v[k];      p2 += hv*g_v[64+k];
            p3 += hv*g_v[128+k];  p4 += hv*g_v[192+k];
        }
        #pragma unroll
        for (int off = 8; off; off >>= 1) {
            p0 += __shfl_xor_sync(0xffffffffu, p0, off);
            p1 += __shfl_xor_sync(0xffffffffu, p1, off);
            p2 += __shfl_xor_sync(0xffffffffu, p2, off);
            p3 += __shfl_xor_sync(0xffffffffu, p3, off);
            p4 += __shfl_xor_sync(0xffffffffu, p4, off);
        }
        if (ln == 0) {
            int row = r0 + lr;
            g_sq[row]  = p0;
            g_s11[row] = p1; g_s21[row] = p2;
            g_s12[row] = p3; g_s22[row] = p4;
        }
    }
}

// ---------------- fused dist + top-7: separate D buffer, 2 barriers/jt ----------------
__global__ void __launch_bounds__(256, 3) knn_kernel() {
    __shared__ __align__(16) float As[64][66];
    __shared__ __align__(16) float Bs[64][66];
    __shared__ __align__(16) float Ds[64][66];   // d2 tile; later cand area
    unsigned long long* cand = (unsigned long long*)&Ds[0][0];  // 14336B < 16896B

    int s = blockIdx.x, itile = blockIdx.y, b = blockIdx.z;
    int i0 = itile*64;
    int t = threadIdx.x;
    for (int q = 0; q < 16; q++) {
        int idx = q*256 + t; int r = idx>>6, c = idx&63;
        As[r][c] = g_feat[(size_t)(b*NN + i0 + r)*64 + c];
    }
    int tx = t&15, ty = t>>4;
    float sqi[4];
    #pragma unroll
    for (int m = 0; m < 4; m++) sqi[m] = g_sq[b*NN + i0 + ty + 16*m];
    int srow = t>>2, sch = t&3;
    float lv[7]; int li[7];
    #pragma unroll
    for (int k = 0; k < 7; k++) { lv[k] = INFINITY; li[k] = 0x7fffffff; }

    for (int jt = 0; jt < JT_PER; jt++) {
        int j0 = (s*JT_PER + jt)*64;
        // load B: safe vs. prev GEMM reads of Bs (post-GEMM sync below);
        // overlaps with prev selection (selection reads Ds only).
        for (int q = 0; q < 16; q++) {
            int idx = q*256 + t; int r = idx>>6, c = idx&63;
            Bs[r][c] = g_feat[(size_t)(b*NN + j0 + r)*64 + c];
        }
        __syncthreads();                       // Bs ready; prev selection done (Ds free)
        unsigned long long acc2[4][4];
        #pragma unroll
        for (int mi = 0; mi < 4; mi++)
            #pragma unroll
            for (int mj = 0; mj < 4; mj++) acc2[mi][mj] = 0ull;
        #pragma unroll 8
        for (int c2 = 0; c2 < 32; c2++) {
            unsigned long long av[4], bv[4];
            #pragma unroll
            for (int m = 0; m < 4; m++) {
                av[m] = *(const unsigned long long*)&As[ty+16*m][2*c2];
                bv[m] = *(const unsigned long long*)&Bs[tx+16*m][2*c2];
            }
            #pragma unroll
            for (int mi = 0; mi < 4; mi++)
                #pragma unroll
                for (int mj = 0; mj < 4; mj++)
                    ffma2(acc2[mi][mj], av[mi], bv[mj]);
        }
        float sqj[4];
        #pragma unroll
        for (int m = 0; m < 4; m++) sqj[m] = g_sq[b*NN + j0 + tx + 16*m];
        #pragma unroll
        for (int mi = 0; mi < 4; mi++)
            #pragma unroll
            for (int mj = 0; mj < 4; mj++) {
                float2 d = *(float2*)&acc2[mi][mj];
                float dot = d.x + d.y;
                Ds[ty+16*mi][tx+16*mj] = fmaxf(sqi[mi] + sqj[mj] - 2.f*dot, 0.f);
            }
        __syncthreads();                       // Ds ready; all GEMM reads of Bs done
        // per-thread candidates arrive in strictly increasing j: strict-< float
        // insertion preserves stable-argsort tie semantics.
        #pragma unroll
        for (int q = 0; q < 16; q++) {
            int jl = sch*16 + q;
            float v = Ds[srow][jl];
            if (v < lv[6]) {
                lv[6] = v; li[6] = j0 + jl;
                #pragma unroll
                for (int p = 6; p > 0; p--) {
                    bool sw = lv[p] < lv[p-1];
                    float tv = lv[p-1]; int ti = li[p-1];
                    lv[p-1] = sw ? lv[p] : lv[p-1];
                    li[p-1] = sw ? li[p] : li[p-1];
                    lv[p]   = sw ? tv : lv[p];
                    li[p]   = sw ? ti : li[p];
                }
            }
        }
    }
    __syncthreads();                           // selections done; Ds free for cand
    #pragma unroll
    for (int k = 0; k < 7; k++)
        cand[srow*28 + sch*7 + k] =
            ((unsigned long long)__float_as_uint(lv[k]) << 32) | (unsigned)li[k];
    __syncthreads();
    if (t < 64) {
        int ptr[4] = {0,0,0,0};
        unsigned long long* c4 = &cand[t*28];
        unsigned long long* go = &g_cand[((size_t)(b*NN + i0 + t)*JSPLIT + s)*KK];
        for (int k = 0; k < KK; k++) {
            int bq = 0; unsigned long long bk = ~0ull;
            #pragma unroll
            for (int q = 0; q < 4; q++) {
                if (ptr[q] < 7) {
                    unsigned long long v = c4[q*7 + ptr[q]];
                    if (v < bk) { bk = v; bq = q; }
                }
            }
            ptr[bq]++;
            go[k] = bk;
        }
    }
}

__global__ void knn_merge_kernel() {
    int row = blockIdx.x*64 + threadIdx.x;
    if (row >= NROWS) return;
    const unsigned long long* c = &g_cand[(size_t)row*JSPLIT*KK];
    int ptr[JSPLIT];
    #pragma unroll
    for (int q = 0; q < JSPLIT; q++) ptr[q] = 0;
    int bbase = (row / NN) * NN;
    for (int k = 0; k < KK; k++) {
        int bq = 0; unsigned long long bk = ~0ull;
        #pragma unroll
        for (int q = 0; q < JSPLIT; q++) {
            if (ptr[q] < KK) {
                unsigned long long v = c[q*KK + ptr[q]];
                if (v < bk) { bk = v; bq = q; }
            }
        }
        ptr[bq]++;
        g_nbr[row*KK + k] = bbase + (int)(bk & 0xffffffffu);
    }
}

// ---------------- fused: head aggregation + output linear + output scores ----------------
__global__ void gat_fused_kernel(const float* __restrict__ Wout) {
    __shared__ float sf[16][128];
    __shared__ int   jn[16][KK];
    __shared__ float e1[16][KK], e2[16][KK];
    int r0 = blockIdx.x*16;
    int g = threadIdx.x >> 6, f = threadIdx.x & 63;

    #pragma unroll
    for (int rr = 0; rr < 4; rr++) {
        int lr = rr*4 + g;
        int row = r0 + lr;
        if (f < KK) {
            int j = g_nbr[row*KK + f];
            jn[lr][f] = j;
            float v1 = g_s11[row] + g_s21[j];
            float v2 = g_s12[row] + g_s22[j];
            e1[lr][f] = v1 > 0.f ? v1 : 0.2f*v1;
            e2[lr][f] = v2 > 0.f ? v2 : 0.2f*v2;
        }
    }
    __syncthreads();
    #pragma unroll
    for (int rr = 0; rr < 4; rr++) {
        int lr = rr*4 + g;
        float m1 = -INFINITY, m2 = -INFINITY;
        #pragma unroll
        for (int k = 0; k < KK; k++) { m1 = fmaxf(m1, e1[lr][k]); m2 = fmaxf(m2, e2[lr][k]); }
        float w1[KK], w2[KK], s1 = 0.f, s2 = 0.f;
        #pragma unroll
        for (int k = 0; k < KK; k++) {
            w1[k] = expf(e1[lr][k]-m1); s1 += w1[k];
            w2[k] = expf(e2[lr][k]-m2); s2 += w2[k];
        }
        float i1 = 1.f/s1, i2 = 1.f/s2;
        float acc1 = 0.f, acc2 = 0.f;
        #pragma unroll
        for (int k = 0; k < KK; k++) {
            int j = jn[lr][k];
            acc1 += (w1[k]*i1)*g_Wh1[(size_t)j*64+f];
            acc2 += (w2[k]*i2)*g_Wh2[(size_t)j*64+f];
        }
        acc1 = acc1 > 0.f ? acc1 : (expf(acc1)-1.f);
        acc2 = acc2 > 0.f ? acc2 : (expf(acc2)-1.f);
        sf[lr][f]      = acc1;
        sf[lr][64 + f] = acc2;
    }
    __syncthreads();
    {
        int rs = threadIdx.x >> 6;
        float acc[4] = {0,0,0,0};
        #pragma unroll 8
        for (int k = 0; k < 128; k++) {
            float wv = Wout[k*64+f];
            #pragma unroll
            for (int r = 0; r < 4; r++) acc[r] += sf[rs*4+r][k]*wv;
        }
        #pragma unroll
        for (int r = 0; r < 4; r++)
            g_Who[(size_t)(r0 + rs*4 + r)*64+f] = acc[r];
    }
    {
        int lr = threadIdx.x >> 4, ln = threadIdx.x & 15;
        float p1 = 0.f, p2 = 0.f;
        #pragma unroll
        for (int q = 0; q < 8; q++) {
            int k = ln*8 + q;
            float hv = sf[lr][k];
            p1 += hv*g_v[256+k]; p2 += hv*g_v[384+k];
        }
        #pragma unroll
        for (int off = 8; off; off >>= 1) {
            p1 += __shfl_xor_sync(0xffffffffu, p1, off);
            p2 += __shfl_xor_sync(0xffffffffu, p2, off);
        }
        if (ln == 0) {
            g_so1[r0 + lr] = p1;
            g_so2[r0 + lr] = p2;
        }
    }
}

// ---------------- output aggregation -> g_gT ----------------
__global__ void gat_out_kernel() {
    int g = threadIdx.x >> 6, f = threadIdx.x & 63;
    int row = blockIdx.x*4 + g;
    __shared__ int   jn[4][KK];
    __shared__ float ee[4][KK];
    if (f < KK) {
        int j = g_nbr[row*KK + f];
        jn[g][f] = j;
        float v = g_so1[row] + g_so2[j];
        ee[g][f] = v > 0.f ? v : 0.2f*v;
    }
    __syncthreads();
    float mx = -INFINITY;
    #pragma unroll
    for (int k = 0; k < KK; k++) mx = fmaxf(mx, ee[g][k]);
    float wk[KK], sum = 0.f;
    #pragma unroll
    for (int k = 0; k < KK; k++) { wk[k] = expf(ee[g][k]-mx); sum += wk[k]; }
    float inv = 1.f/sum, acc = 0.f;
    #pragma unroll
    for (int k = 0; k < KK; k++) acc += (wk[k]*inv)*g_Who[(size_t)jn[g][k]*64+f];
    acc = acc > 0.f ? acc : (expf(acc)-1.f);
    int b = row / NN, n = row % NN;
    g_gT[(size_t)(b*64 + f)*NN + n] = acc;
}

// ---------------- transpose conv: parity-class blocking + 8-co tiling ----------------
__global__ void tconv_kernel(const float* __restrict__ tw, const float* __restrict__ bias,
                             float* __restrict__ out) {
    __shared__ float ws[8*576];
    int co0 = blockIdx.y*8;
    for (int idx = threadIdx.x; idx < 8*576; idx += 256) {
        int co_l = idx/576, rem = idx%576, ci = rem/9, q = rem%9;
        ws[idx] = tw[((size_t)(ci*64 + co0 + co_l))*9 + q];
    }
    __syncthreads();

    int cls = blockIdx.z;
    int px = cls & 1, py = cls >> 1;
    int p2 = blockIdx.x*256 + threadIdx.x;
    int xw = p2 % HH;
    int yh = (p2 / HH) % HH;
    int b  = p2 / (HH*HH);
    int ow = 2*xw + px, oh = 2*yh + py;

    float acc[8];
    #pragma unroll
    for (int c = 0; c < 8; c++) acc[c] = bias[co0+c];

    const float* gbase = g_gT + (size_t)b*64*NN;
    #pragma unroll
    for (int kh = 0; kh < 3; kh++) {
        int t_ = oh + 1 - kh;
        if (t_ & 1) continue;
        int ih = t_ >> 1; if ((unsigned)ih >= HH) continue;
        #pragma unroll
        for (int kw = 0; kw < 3; kw++) {
            int u = ow + 1 - kw;
            if (u & 1) continue;
            int iw = u >> 1; if ((unsigned)iw >= HH) continue;
            const float* gp = gbase + ih*HH + iw;
            int qq = kh*3 + kw;
            #pragma unroll 8
            for (int ci = 0; ci < 64; ci++) {
                float gv = gp[(size_t)ci*NN];
                #pragma unroll
                for (int c = 0; c < 8; c++) acc[c] += gv * ws[c*576 + ci*9 + qq];
            }
        }
    }
    #pragma unroll
    for (int c = 0; c < 8; c++)
        out[((size_t)(b*64 + co0 + c))*(HIN*HIN) + oh*HIN + ow] = acc[c];
}

// ---------------- launcher ----------------
extern "C" void kernel_launch(void* const* d_in, const int* in_sizes, int n_in,
                              void* d_out, int out_size) {
    const float* x       = (const float*)d_in[0];
    const float* conv_w  = (const float*)d_in[1];
    const float* conv_b  = (const float*)d_in[2];
    const float* W1      = (const float*)d_in[3];
    const float* a1      = (const float*)d_in[4];
    const float* W2      = (const float*)d_in[5];
    const float* a2      = (const float*)d_in[6];
    const float* Wout    = (const float*)d_in[7];
    const float* aout    = (const float*)d_in[8];
    const float* tconv_w = (const float*)d_in[9];
    const float* tconv_b = (const float*)d_in[10];
    float* out = (float*)d_out;

    prep_vecs_kernel<<<1, 128>>>(W1, a1, W2, a2, Wout, aout);
    conv_kernel<<<dim3(36, 8), 128>>>(x, conv_w, conv_b);
    stats_linear_kernel<<<NROWS/16, 256>>>(W1, W2);
    knn_kernel<<<dim3(JSPLIT, 36, 2), 256>>>();
    knn_merge_kernel<<<NROWS/64, 64>>>();
    gat_fused_kernel<<<NROWS/16, 256>>>(Wout);
    gat_out_kernel<<<NROWS/4, 256>>>();
    tconv_kernel<<<dim3(18, 8, 4), 256>>>(tconv_w, tconv_b, out);
}